// round 1
// baseline (speedup 1.0000x reference)
#include <cuda_runtime.h>
#include <cuda_bf16.h>

// ---------------------------------------------------------------------------
// MultiHeadAttention: B=2, S=2048, D_MODEL=1024, H=16, Dk=64
// Round 1: fp32 SIMT baseline.
//   1) proj_kernel   : q/k/v = X @ W^T + b   (head-split layout)     [grid.z=3]
//   2) scores_kernel : S = 0.125 * q k^T  per (b,h)   -> g_scores
//   3) softmax_kernel: row softmax in-place
//   4) pv_kernel     : ctx = S @ v  per (b,h), merged-head layout
//   5) out_kernel    : out = ctx @ Wo^T + bo
// ---------------------------------------------------------------------------

#define B_    2
#define S_    2048
#define H_    16
#define DK    64
#define DM    1024
#define MROWS (B_ * S_)   // 4096
#define BH    (B_ * H_)   // 32

// Static scratch (no dynamic allocation allowed).
__device__ float g_q[BH * S_ * DK];                 // 16 MB
__device__ float g_k[BH * S_ * DK];                 // 16 MB
__device__ float g_v[BH * S_ * DK];                 // 16 MB
__device__ float g_scores[(size_t)BH * S_ * S_];    // 512 MB
__device__ float g_ctx[(size_t)MROWS * DM];         // 16 MB

// ---------------------------------------------------------------------------
// Generic 64x64 tile GEMM core, 256 threads, 4x4 per-thread register tile.
// Computes acc = A_tile (64xK) * op(B) where:
//   BT=true : C = A * B^T, B stored [N][K] row-major (both operands K-major)
//   BT=false: C = A * B,   B stored [K][N] row-major
// A points at the tile's first row; B points at the tile's first row (BT)
// or at column offset n0 (non-BT). K must be a multiple of 16.
// ---------------------------------------------------------------------------
template <bool BT>
__device__ __forceinline__ void gemm_core(
    const float* __restrict__ A, int lda,
    const float* __restrict__ B, int ldb,
    int K, float (&As)[16][64], float (&Bs)[16][64], float (&acc)[4][4])
{
    const int tid = threadIdx.x;
    const int tx  = tid & 15;          // 0..15 (n)
    const int ty  = tid >> 4;          // 0..15 (m)
    const int lm  = tid >> 2;          // 0..63  (row for K-major loads)
    const int lk  = (tid & 3) << 2;    // 0,4,8,12
    const int kr  = tid >> 4;          // 0..15  (k-row for [K][N] B loads)
    const int nc  = (tid & 15) << 2;   // 0..60

#pragma unroll
    for (int i = 0; i < 4; i++)
#pragma unroll
        for (int j = 0; j < 4; j++) acc[i][j] = 0.f;

    for (int k0 = 0; k0 < K; k0 += 16) {
        float4 av = *(const float4*)(A + (size_t)lm * lda + k0 + lk);
        float4 bv;
        if (BT) bv = *(const float4*)(B + (size_t)lm * ldb + k0 + lk);
        else    bv = *(const float4*)(B + (size_t)(k0 + kr) * ldb + nc);

        __syncthreads();   // previous iteration's reads must finish
        As[lk + 0][lm] = av.x;
        As[lk + 1][lm] = av.y;
        As[lk + 2][lm] = av.z;
        As[lk + 3][lm] = av.w;
        if (BT) {
            Bs[lk + 0][lm] = bv.x;
            Bs[lk + 1][lm] = bv.y;
            Bs[lk + 2][lm] = bv.z;
            Bs[lk + 3][lm] = bv.w;
        } else {
            *(float4*)&Bs[kr][nc] = bv;
        }
        __syncthreads();

#pragma unroll
        for (int kk = 0; kk < 16; kk++) {
            float4 a4 = *(const float4*)&As[kk][ty << 2];
            float4 b4 = *(const float4*)&Bs[kk][tx << 2];
            float ar[4] = {a4.x, a4.y, a4.z, a4.w};
            float br[4] = {b4.x, b4.y, b4.z, b4.w};
#pragma unroll
            for (int i = 0; i < 4; i++)
#pragma unroll
                for (int j = 0; j < 4; j++)
                    acc[i][j] = fmaf(ar[i], br[j], acc[i][j]);
        }
    }
}

// ---------------------------------------------------------------------------
// 1) QKV projections. grid = (16, 64, 3); z selects which projection.
//    Output in head-split layout: out[((b*H+h)*S + s)*DK + dk]
// ---------------------------------------------------------------------------
__global__ void proj_kernel(
    const float* __restrict__ Q, const float* __restrict__ Kin,
    const float* __restrict__ V,
    const float* __restrict__ Wq, const float* __restrict__ bq,
    const float* __restrict__ Wk, const float* __restrict__ bk,
    const float* __restrict__ Wv, const float* __restrict__ bv)
{
    __shared__ float As[16][64];
    __shared__ float Bs[16][64];

    const float* X; const float* W; const float* bias; float* out;
    if (blockIdx.z == 0)      { X = Q;   W = Wq; bias = bq; out = g_q; }
    else if (blockIdx.z == 1) { X = Kin; W = Wk; bias = bk; out = g_k; }
    else                      { X = V;   W = Wv; bias = bv; out = g_v; }

    const int m0 = blockIdx.y * 64;
    const int n0 = blockIdx.x * 64;

    float acc[4][4];
    gemm_core<true>(X + (size_t)m0 * DM, DM, W + (size_t)n0 * DM, DM, DM, As, Bs, acc);

    const int tx = threadIdx.x & 15, ty = threadIdx.x >> 4;
#pragma unroll
    for (int i = 0; i < 4; i++) {
        const int m = m0 + (ty << 2) + i;
        const int b = m >> 11;          // m / 2048
        const int s = m & (S_ - 1);
#pragma unroll
        for (int j = 0; j < 4; j++) {
            const int n  = n0 + (tx << 2) + j;
            const int h  = n >> 6;
            const int dk = n & 63;
            out[(((size_t)(b * H_ + h) * S_) + s) * DK + dk] = acc[i][j] + bias[n];
        }
    }
}

// ---------------------------------------------------------------------------
// 2) scores = 0.125 * q k^T per (b,h). grid = (32, 32, 32); z = bh.
// ---------------------------------------------------------------------------
__global__ void scores_kernel()
{
    __shared__ float As[16][64];
    __shared__ float Bs[16][64];

    const int bh = blockIdx.z;
    const float* A = g_q + (size_t)bh * S_ * DK;
    const float* B = g_k + (size_t)bh * S_ * DK;
    float*       C = g_scores + (size_t)bh * S_ * S_;

    const int m0 = blockIdx.y * 64;
    const int n0 = blockIdx.x * 64;

    float acc[4][4];
    gemm_core<true>(A + (size_t)m0 * DK, DK, B + (size_t)n0 * DK, DK, DK, As, Bs, acc);

    const int tx = threadIdx.x & 15, ty = threadIdx.x >> 4;
#pragma unroll
    for (int i = 0; i < 4; i++) {
        const int m = m0 + (ty << 2) + i;
#pragma unroll
        for (int j = 0; j < 4; j++) {
            const int n = n0 + (tx << 2) + j;
            C[(size_t)m * S_ + n] = acc[i][j] * 0.125f;   // 1/sqrt(64)
        }
    }
}

// ---------------------------------------------------------------------------
// 3) Row softmax, in place. grid = BH*S_ = 65536 blocks, 256 threads.
// ---------------------------------------------------------------------------
__global__ void softmax_kernel()
{
    float* p = g_scores + (size_t)blockIdx.x * S_;
    const int tid = threadIdx.x;

    float v[8];
    float mx = -1e30f;
#pragma unroll
    for (int i = 0; i < 8; i++) {
        v[i] = p[tid + 256 * i];
        mx = fmaxf(mx, v[i]);
    }

    __shared__ float red[8];
#pragma unroll
    for (int o = 16; o > 0; o >>= 1)
        mx = fmaxf(mx, __shfl_xor_sync(0xffffffffu, mx, o));
    if ((tid & 31) == 0) red[tid >> 5] = mx;
    __syncthreads();
    mx = red[0];
#pragma unroll
    for (int w = 1; w < 8; w++) mx = fmaxf(mx, red[w]);

    float s = 0.f;
#pragma unroll
    for (int i = 0; i < 8; i++) {
        v[i] = __expf(v[i] - mx);
        s += v[i];
    }
#pragma unroll
    for (int o = 16; o > 0; o >>= 1)
        s += __shfl_xor_sync(0xffffffffu, s, o);
    __syncthreads();                     // before reusing red[]
    if ((tid & 31) == 0) red[tid >> 5] = s;
    __syncthreads();
    s = 0.f;
#pragma unroll
    for (int w = 0; w < 8; w++) s += red[w];

    const float inv = 1.0f / s;
#pragma unroll
    for (int i = 0; i < 8; i++) p[tid + 256 * i] = v[i] * inv;
}

// ---------------------------------------------------------------------------
// 4) ctx = attn @ v per (b,h). grid = (1, 32, 32); z = bh. B is [K][N] -> BT=false.
//    Writes merged-head layout: ctx[(b*S+s)*DM + h*DK + d]
// ---------------------------------------------------------------------------
__global__ void pv_kernel()
{
    __shared__ float As[16][64];
    __shared__ float Bs[16][64];

    const int bh = blockIdx.z;
    const float* A = g_scores + (size_t)bh * S_ * S_;   // [S][S]
    const float* B = g_v      + (size_t)bh * S_ * DK;   // [S][DK]

    const int m0 = blockIdx.y * 64;
    const int n0 = blockIdx.x * 64;   // always 0 (DK == 64)

    float acc[4][4];
    gemm_core<false>(A + (size_t)m0 * S_, S_, B + n0, DK, S_, As, Bs, acc);

    const int b = bh >> 4;
    const int h = bh & 15;
    const int tx = threadIdx.x & 15, ty = threadIdx.x >> 4;
#pragma unroll
    for (int i = 0; i < 4; i++) {
        const int s = m0 + (ty << 2) + i;
#pragma unroll
        for (int j = 0; j < 4; j++) {
            const int d = n0 + (tx << 2) + j;
            g_ctx[(size_t)(b * S_ + s) * DM + h * DK + d] = acc[i][j];
        }
    }
}

// ---------------------------------------------------------------------------
// 5) out = ctx @ Wo^T + bo. grid = (16, 64, 1).
// ---------------------------------------------------------------------------
__global__ void out_kernel(float* __restrict__ out,
                           const float* __restrict__ Wo,
                           const float* __restrict__ bo)
{
    __shared__ float As[16][64];
    __shared__ float Bs[16][64];

    const int m0 = blockIdx.y * 64;
    const int n0 = blockIdx.x * 64;

    float acc[4][4];
    gemm_core<true>(g_ctx + (size_t)m0 * DM, DM, Wo + (size_t)n0 * DM, DM, DM, As, Bs, acc);

    const int tx = threadIdx.x & 15, ty = threadIdx.x >> 4;
#pragma unroll
    for (int i = 0; i < 4; i++) {
        const int m = m0 + (ty << 2) + i;
#pragma unroll
        for (int j = 0; j < 4; j++) {
            const int n = n0 + (tx << 2) + j;
            out[(size_t)m * DM + n] = acc[i][j] + bo[n];
        }
    }
}

// ---------------------------------------------------------------------------
// Launcher. Inputs (metadata order): Q K V Wq bq Wk bk Wv bv Wo bo (all f32).
// ---------------------------------------------------------------------------
extern "C" void kernel_launch(void* const* d_in, const int* in_sizes, int n_in,
                              void* d_out, int out_size)
{
    (void)in_sizes; (void)n_in; (void)out_size;
    const float* Q   = (const float*)d_in[0];
    const float* K   = (const float*)d_in[1];
    const float* V   = (const float*)d_in[2];
    const float* Wq  = (const float*)d_in[3];
    const float* bq  = (const float*)d_in[4];
    const float* Wk  = (const float*)d_in[5];
    const float* bk  = (const float*)d_in[6];
    const float* Wv  = (const float*)d_in[7];
    const float* bv  = (const float*)d_in[8];
    const float* Wo  = (const float*)d_in[9];
    const float* bo  = (const float*)d_in[10];
    float* out = (float*)d_out;

    dim3 blk(256);
    proj_kernel<<<dim3(DM / 64, MROWS / 64, 3), blk>>>(Q, K, V, Wq, bq, Wk, bk, Wv, bv);
    scores_kernel<<<dim3(S_ / 64, S_ / 64, BH), blk>>>();
    softmax_kernel<<<dim3(BH * S_), blk>>>();
    pv_kernel<<<dim3(DK / 64, S_ / 64, BH), blk>>>();
    out_kernel<<<dim3(DM / 64, MROWS / 64, 1), blk>>>(out, Wo, bo);
}

// round 6
// speedup vs baseline: 1.7190x; 1.7190x over previous
#include <cuda_runtime.h>
#include <cuda_bf16.h>
#include <cstdint>

// ===========================================================================
// MHA  B=2 S=2048 DM=1024 H=16 DK=64 — Round 6: all-HMMA split-bf16 pipeline
// (R4 design) + cvt fix: __device__ symbols are resolved INSIDE device code.
// (Passing g_X from host passed the host-shadow address; on GB300 ATS makes
//  that a valid pointer into host RAM, so cvt silently wrote to the void.)
// C = Ah*Bh + Ah*Bl + Al*Bh, fp32 accumulate.
// ===========================================================================

#define B_    2
#define S_    2048
#define H_    16
#define DK    64
#define DM    1024
#define MROWS (B_ * S_)   // 4096
#define BH    (B_ * H_)   // 32

// ---------------- device scratch (static; no dynamic alloc) ----------------
__device__ __nv_bfloat16 g_Qhi[MROWS * DM], g_Qlo[MROWS * DM];
__device__ __nv_bfloat16 g_Khi[MROWS * DM], g_Klo[MROWS * DM];
__device__ __nv_bfloat16 g_Vhi[MROWS * DM], g_Vlo[MROWS * DM];
__device__ __nv_bfloat16 g_Wqhi[DM * DM], g_Wqlo[DM * DM];
__device__ __nv_bfloat16 g_Wkhi[DM * DM], g_Wklo[DM * DM];
__device__ __nv_bfloat16 g_Wvhi[DM * DM], g_Wvlo[DM * DM];
__device__ __nv_bfloat16 g_Wohi[DM * DM], g_Wolo[DM * DM];
__device__ __nv_bfloat16 g_qhi[BH * S_ * DK], g_qlo[BH * S_ * DK];
__device__ __nv_bfloat16 g_khi[BH * S_ * DK], g_klo[BH * S_ * DK];
__device__ __nv_bfloat16 g_vThi[BH * DK * S_], g_vTlo[BH * DK * S_];
__device__ float         g_scores[(size_t)BH * S_ * S_];          // 512 MB
__device__ __nv_bfloat16 g_ctxhi[MROWS * DM], g_ctxlo[MROWS * DM];

// ---------------- helpers ----------------
__device__ __forceinline__ uint32_t smem_u32(const void* p) {
    uint32_t a;
    asm("{ .reg .u64 t; cvta.to.shared.u64 t, %1; cvt.u32.u64 %0, t; }" : "=r"(a) : "l"(p));
    return a;
}
#define SWZ(b) ((b) ^ (((b) >> 3) & 0x70))

__device__ __forceinline__ uint32_t lds32(uint32_t addr) {
    uint32_t v;
    asm volatile("ld.shared.b32 %0, [%1];" : "=r"(v) : "r"(addr));
    return v;
}
__device__ __forceinline__ void sts128(uint32_t addr, uint4 v) {
    asm volatile("st.shared.v4.b32 [%0], {%1,%2,%3,%4};"
        :: "r"(addr), "r"(v.x), "r"(v.y), "r"(v.z), "r"(v.w) : "memory");
}
__device__ __forceinline__ void hmma(float c[4], const uint32_t a[4], const uint32_t b[2]) {
    asm volatile("mma.sync.aligned.m16n8k16.row.col.f32.bf16.bf16.f32 "
        "{%0,%1,%2,%3}, {%4,%5,%6,%7}, {%8,%9}, {%0,%1,%2,%3};"
        : "+f"(c[0]), "+f"(c[1]), "+f"(c[2]), "+f"(c[3])
        : "r"(a[0]), "r"(a[1]), "r"(a[2]), "r"(a[3]), "r"(b[0]), "r"(b[1]));
}
__device__ __forceinline__ uint32_t pk2(__nv_bfloat16 a, __nv_bfloat16 b) {
    return (uint32_t)__bfloat16_as_ushort(a) | ((uint32_t)__bfloat16_as_ushort(b) << 16);
}
__device__ __forceinline__ void split2(float x, __nv_bfloat16& h, __nv_bfloat16& l) {
    h = __float2bfloat16(x);
    l = __float2bfloat16(x - __bfloat162float(h));
}

// ---------------- smem tile layout (static 48 KB) ----------------
#define SM_AHI 0
#define SM_ALO 16384
#define SM_BHI 32768
#define SM_BLO 40960
#define SM_SZ  49152

// ---------------------------------------------------------------------------
// Mainloop: acc(128x64 block; warp 32x32) += 3-pass split MMA over K.
// A: 128 x K (K-major), B: 64 x K (K-major). 256 threads, warps 4(m) x 2(n).
// Direct ld.shared fragment loads at the PTX mma.m16n8k16 table coordinates.
// ---------------------------------------------------------------------------
template <bool AF32>
__device__ __forceinline__ void mma_loop(
    const void* Ah_, const void* Al_, int lda,
    const __nv_bfloat16* __restrict__ Bh, const __nv_bfloat16* __restrict__ Bl,
    int ldb, int K, char* sm, float acc[2][4][4])
{
    const int tid  = threadIdx.x;
    const int lane = tid & 31;
    const int wid  = tid >> 5;
    const int wm   = wid >> 1;       // 0..3
    const int wn   = wid & 1;        // 0..1
    const uint32_t smb = smem_u32(sm);

    const int g  = lane >> 2;
    const int tb = (lane & 3) << 2;  // byte offset of this thread's k-pair

    const int nch = K >> 6;
    for (int ch = 0; ch < nch; ch++) {
        const int k0 = ch << 6;
        __syncthreads();                 // all warps done reading prev chunk

        // ---- fill A (128x64) hi/lo ----
        if (AF32) {
            const float* A = (const float*)Ah_;
#pragma unroll
            for (int i = 0; i < 4; i++) {
                int e = (tid + (i << 8)) << 3;
                int row = e >> 6, col = e & 63;
                const float4* gp = (const float4*)(A + (size_t)row * lda + k0 + col);
                float4 v0 = gp[0], v1 = gp[1];
                __nv_bfloat16 h[8], l[8];
                split2(v0.x, h[0], l[0]); split2(v0.y, h[1], l[1]);
                split2(v0.z, h[2], l[2]); split2(v0.w, h[3], l[3]);
                split2(v1.x, h[4], l[4]); split2(v1.y, h[5], l[5]);
                split2(v1.z, h[6], l[6]); split2(v1.w, h[7], l[7]);
                uint4 uh = { pk2(h[0],h[1]), pk2(h[2],h[3]), pk2(h[4],h[5]), pk2(h[6],h[7]) };
                uint4 ul = { pk2(l[0],l[1]), pk2(l[2],l[3]), pk2(l[4],l[5]), pk2(l[6],l[7]) };
                uint32_t sw = SWZ((uint32_t)(row * 128 + col * 2));
                sts128(smb + SM_AHI + sw, uh);
                sts128(smb + SM_ALO + sw, ul);
            }
        } else {
            const __nv_bfloat16* Ah = (const __nv_bfloat16*)Ah_;
            const __nv_bfloat16* Al = (const __nv_bfloat16*)Al_;
#pragma unroll
            for (int i = 0; i < 4; i++) {
                int e = (tid + (i << 8)) << 3;
                int row = e >> 6, col = e & 63;
                uint4 uh = *(const uint4*)(Ah + (size_t)row * lda + k0 + col);
                uint4 ul = *(const uint4*)(Al + (size_t)row * lda + k0 + col);
                uint32_t sw = SWZ((uint32_t)(row * 128 + col * 2));
                sts128(smb + SM_AHI + sw, uh);
                sts128(smb + SM_ALO + sw, ul);
            }
        }
        // ---- fill B (64x64) hi/lo ----
#pragma unroll
        for (int i = 0; i < 2; i++) {
            int e = (tid + (i << 8)) << 3;
            int row = e >> 6, col = e & 63;
            uint4 uh = *(const uint4*)(Bh + (size_t)row * ldb + k0 + col);
            uint4 ul = *(const uint4*)(Bl + (size_t)row * ldb + k0 + col);
            uint32_t sw = SWZ((uint32_t)(row * 128 + col * 2));
            sts128(smb + SM_BHI + sw, uh);
            sts128(smb + SM_BLO + sw, ul);
        }
        __syncthreads();

        // ---- 3 passes: (Ah,Bh), (Ah,Bl), (Al,Bh) ----
#pragma unroll
        for (int p = 0; p < 3; p++) {
            const uint32_t Ab = smb + ((p == 2) ? SM_ALO : SM_AHI);
            const uint32_t Bb = smb + ((p == 1) ? SM_BLO : SM_BHI);
#pragma unroll
            for (int ks = 0; ks < 4; ks++) {
                const uint32_t kb = (uint32_t)(ks * 32);
                uint32_t a[2][4], bb[4][2];
#pragma unroll
                for (int i = 0; i < 2; i++) {
                    const uint32_t r0 = (uint32_t)(wm * 32 + i * 16 + g);
                    a[i][0] = lds32(Ab + SWZ(r0 * 128       + kb      + tb));
                    a[i][1] = lds32(Ab + SWZ((r0 + 8) * 128 + kb      + tb));
                    a[i][2] = lds32(Ab + SWZ(r0 * 128       + kb + 16 + tb));
                    a[i][3] = lds32(Ab + SWZ((r0 + 8) * 128 + kb + 16 + tb));
                }
#pragma unroll
                for (int j = 0; j < 4; j++) {
                    const uint32_t rn = (uint32_t)(wn * 32 + j * 8 + g);
                    bb[j][0] = lds32(Bb + SWZ(rn * 128 + kb      + tb));
                    bb[j][1] = lds32(Bb + SWZ(rn * 128 + kb + 16 + tb));
                }
#pragma unroll
                for (int i = 0; i < 2; i++)
#pragma unroll
                    for (int j = 0; j < 4; j++)
                        hmma(acc[i][j], a[i], bb[j]);
            }
        }
    }
}

// D fragment: element (i,j,half,q) -> row m0+wm*32+i*16+(lane>>2)+half*8,
//                                    col n0+wn*32+j*8+2*(lane&3)+q.

// ---------------------------------------------------------------------------
// cvt: fp32 -> (hi, lo) bf16. Destination selected INSIDE device code.
//   which: 0..2 -> Q,K,V (nX4)   3..6 -> Wq,Wk,Wv,Wo (nW4)
// ---------------------------------------------------------------------------
__global__ void cvt_kernel(const float* __restrict__ src, int which, int n4)
{
    int i = blockIdx.x * blockDim.x + threadIdx.x;
    if (i >= n4) return;

    __nv_bfloat16 *hi, *lo;
    switch (which) {
        case 0: hi = g_Qhi;  lo = g_Qlo;  break;
        case 1: hi = g_Khi;  lo = g_Klo;  break;
        case 2: hi = g_Vhi;  lo = g_Vlo;  break;
        case 3: hi = g_Wqhi; lo = g_Wqlo; break;
        case 4: hi = g_Wkhi; lo = g_Wklo; break;
        case 5: hi = g_Wvhi; lo = g_Wvlo; break;
        default: hi = g_Wohi; lo = g_Wolo; break;
    }

    float4 v = ((const float4*)src)[i];
    __nv_bfloat16 h[4], l[4];
    split2(v.x, h[0], l[0]); split2(v.y, h[1], l[1]);
    split2(v.z, h[2], l[2]); split2(v.w, h[3], l[3]);
    uint2 uh = { pk2(h[0], h[1]), pk2(h[2], h[3]) };
    uint2 ul = { pk2(l[0], l[1]), pk2(l[2], l[3]) };
    ((uint2*)hi)[i] = uh;
    ((uint2*)lo)[i] = ul;
}

// ---------------------------------------------------------------------------
// proj: z in {0,1,2} -> q, k (head-split), vT (transposed). grid (16, 32, 3)
// ---------------------------------------------------------------------------
__global__ __launch_bounds__(256) void proj_kernel(
    const float* __restrict__ bq, const float* __restrict__ bk,
    const float* __restrict__ bv)
{
    __shared__ char sm[SM_SZ];
    const int z  = blockIdx.z;
    const int n0 = blockIdx.x * 64;
    const int m0 = blockIdx.y * 128;

    const __nv_bfloat16 *Ah, *Al, *Bh, *Bl;
    const float* bias;
    if (z == 0)      { Ah = g_Qhi; Al = g_Qlo; Bh = g_Wqhi; Bl = g_Wqlo; bias = bq; }
    else if (z == 1) { Ah = g_Khi; Al = g_Klo; Bh = g_Wkhi; Bl = g_Wklo; bias = bk; }
    else             { Ah = g_Vhi; Al = g_Vlo; Bh = g_Wvhi; Bl = g_Wvlo; bias = bv; }

    float acc[2][4][4];
#pragma unroll
    for (int i = 0; i < 2; i++)
#pragma unroll
        for (int j = 0; j < 4; j++)
#pragma unroll
            for (int q = 0; q < 4; q++) acc[i][j][q] = 0.f;

    mma_loop<false>(Ah + (size_t)m0 * DM, Al + (size_t)m0 * DM, DM,
                    Bh + (size_t)n0 * DM, Bl + (size_t)n0 * DM, DM, DM, sm, acc);

    const int lane = threadIdx.x & 31, wid = threadIdx.x >> 5;
    const int wm = wid >> 1, wn = wid & 1;
#pragma unroll
    for (int i = 0; i < 2; i++)
#pragma unroll
    for (int half = 0; half < 2; half++) {
        const int r = m0 + wm * 32 + i * 16 + (lane >> 2) + half * 8;
        const int b = r >> 11, s = r & (S_ - 1);
#pragma unroll
        for (int j = 0; j < 4; j++)
#pragma unroll
        for (int q = 0; q < 2; q++) {
            const int n = n0 + wn * 32 + j * 8 + 2 * (lane & 3) + q;
            float v = acc[i][j][half * 2 + q] + bias[n];
            __nv_bfloat16 h, l; split2(v, h, l);
            const int hh = n >> 6, dk = n & 63;
            const size_t bh = (size_t)(b * H_ + hh);
            if (z == 0) {
                g_qhi[(bh * S_ + s) * DK + dk] = h;
                g_qlo[(bh * S_ + s) * DK + dk] = l;
            } else if (z == 1) {
                g_khi[(bh * S_ + s) * DK + dk] = h;
                g_klo[(bh * S_ + s) * DK + dk] = l;
            } else {
                g_vThi[(bh * DK + dk) * S_ + s] = h;
                g_vTlo[(bh * DK + dk) * S_ + s] = l;
            }
        }
    }
}

// ---------------------------------------------------------------------------
// scores: fp32 scores = 0.125 * q k^T.  grid (32, 16, BH)
// ---------------------------------------------------------------------------
__global__ __launch_bounds__(256) void scores_kernel()
{
    __shared__ char sm[SM_SZ];
    const int bh = blockIdx.z;
    const int n0 = blockIdx.x * 64;
    const int m0 = blockIdx.y * 128;
    const size_t off = (size_t)bh * S_ * DK;

    float acc[2][4][4];
#pragma unroll
    for (int i = 0; i < 2; i++)
#pragma unroll
        for (int j = 0; j < 4; j++)
#pragma unroll
            for (int q = 0; q < 4; q++) acc[i][j][q] = 0.f;

    mma_loop<false>(g_qhi + off + (size_t)m0 * DK, g_qlo + off + (size_t)m0 * DK, DK,
                    g_khi + off + (size_t)n0 * DK, g_klo + off + (size_t)n0 * DK, DK,
                    DK, sm, acc);

    float* C = g_scores + (size_t)bh * S_ * S_;
    const int lane = threadIdx.x & 31, wid = threadIdx.x >> 5;
    const int wm = wid >> 1, wn = wid & 1;
#pragma unroll
    for (int i = 0; i < 2; i++)
#pragma unroll
    for (int half = 0; half < 2; half++) {
        const int r = m0 + wm * 32 + i * 16 + (lane >> 2) + half * 8;
#pragma unroll
        for (int j = 0; j < 4; j++) {
            const int c = n0 + wn * 32 + j * 8 + 2 * (lane & 3);
            float2 o = { acc[i][j][half * 2] * 0.125f, acc[i][j][half * 2 + 1] * 0.125f };
            *(float2*)(C + (size_t)r * S_ + c) = o;
        }
    }
}

// ---------------------------------------------------------------------------
// softmax: fp32 in place. grid BH*S blocks, 256 threads
// ---------------------------------------------------------------------------
__global__ void softmax_kernel()
{
    float* p = g_scores + (size_t)blockIdx.x * S_;
    const int tid = threadIdx.x;

    float v[8];
    float mx = -1e30f;
#pragma unroll
    for (int i = 0; i < 8; i++) { v[i] = p[tid + 256 * i]; mx = fmaxf(mx, v[i]); }

    __shared__ float red[8];
#pragma unroll
    for (int o = 16; o > 0; o >>= 1) mx = fmaxf(mx, __shfl_xor_sync(~0u, mx, o));
    if ((tid & 31) == 0) red[tid >> 5] = mx;
    __syncthreads();
    mx = red[0];
#pragma unroll
    for (int w = 1; w < 8; w++) mx = fmaxf(mx, red[w]);

    float s = 0.f;
#pragma unroll
    for (int i = 0; i < 8; i++) { v[i] = __expf(v[i] - mx); s += v[i]; }
#pragma unroll
    for (int o = 16; o > 0; o >>= 1) s += __shfl_xor_sync(~0u, s, o);
    __syncthreads();
    if ((tid & 31) == 0) red[tid >> 5] = s;
    __syncthreads();
    s = 0.f;
#pragma unroll
    for (int w = 0; w < 8; w++) s += red[w];

    const float inv = 1.0f / s;
#pragma unroll
    for (int i = 0; i < 8; i++) p[tid + 256 * i] = v[i] * inv;
}

// ---------------------------------------------------------------------------
// pv: ctx(hi/lo) = P @ V.  A = fp32 probs (inline split), B = vT. grid (1,16,BH)
// ---------------------------------------------------------------------------
__global__ __launch_bounds__(256) void pv_kernel()
{
    __shared__ char sm[SM_SZ];
    const int bh = blockIdx.z;
    const int m0 = blockIdx.y * 128;
    const float* A = g_scores + (size_t)bh * S_ * S_ + (size_t)m0 * S_;
    const size_t voff = (size_t)bh * DK * S_;

    float acc[2][4][4];
#pragma unroll
    for (int i = 0; i < 2; i++)
#pragma unroll
        for (int j = 0; j < 4; j++)
#pragma unroll
            for (int q = 0; q < 4; q++) acc[i][j][q] = 0.f;

    mma_loop<true>(A, nullptr, S_, g_vThi + voff, g_vTlo + voff, S_, S_, sm, acc);

    const int b = bh >> 4, h = bh & 15;
    const int lane = threadIdx.x & 31, wid = threadIdx.x >> 5;
    const int wm = wid >> 1, wn = wid & 1;
#pragma unroll
    for (int i = 0; i < 2; i++)
#pragma unroll
    for (int half = 0; half < 2; half++) {
        const int s = m0 + wm * 32 + i * 16 + (lane >> 2) + half * 8;
        const size_t rowoff = ((size_t)(b * S_ + s)) * DM + h * DK;
#pragma unroll
        for (int j = 0; j < 4; j++)
#pragma unroll
        for (int q = 0; q < 2; q++) {
            const int d = wn * 32 + j * 8 + 2 * (lane & 3) + q;
            __nv_bfloat16 hh, ll; split2(acc[i][j][half * 2 + q], hh, ll);
            g_ctxhi[rowoff + d] = hh;
            g_ctxlo[rowoff + d] = ll;
        }
    }
}

// ---------------------------------------------------------------------------
// out: out = ctx @ Wo^T + bo.  grid (16, 32)
// ---------------------------------------------------------------------------
__global__ __launch_bounds__(256) void out_kernel(float* __restrict__ out,
                                                  const float* __restrict__ bo)
{
    __shared__ char sm[SM_SZ];
    const int n0 = blockIdx.x * 64;
    const int m0 = blockIdx.y * 128;

    float acc[2][4][4];
#pragma unroll
    for (int i = 0; i < 2; i++)
#pragma unroll
        for (int j = 0; j < 4; j++)
#pragma unroll
            for (int q = 0; q < 4; q++) acc[i][j][q] = 0.f;

    mma_loop<false>(g_ctxhi + (size_t)m0 * DM, g_ctxlo + (size_t)m0 * DM, DM,
                    g_Wohi + (size_t)n0 * DM, g_Wolo + (size_t)n0 * DM, DM, DM, sm, acc);

    const int lane = threadIdx.x & 31, wid = threadIdx.x >> 5;
    const int wm = wid >> 1, wn = wid & 1;
#pragma unroll
    for (int i = 0; i < 2; i++)
#pragma unroll
    for (int half = 0; half < 2; half++) {
        const int r = m0 + wm * 32 + i * 16 + (lane >> 2) + half * 8;
#pragma unroll
        for (int j = 0; j < 4; j++) {
            const int c = n0 + wn * 32 + j * 8 + 2 * (lane & 3);
            float2 o = { acc[i][j][half * 2] + bo[c],
                         acc[i][j][half * 2 + 1] + bo[c + 1] };
            *(float2*)(out + (size_t)r * DM + c) = o;
        }
    }
}

// ---------------------------------------------------------------------------
// launcher — NOTE: no __device__ symbol is referenced from host code.
// ---------------------------------------------------------------------------
extern "C" void kernel_launch(void* const* d_in, const int* in_sizes, int n_in,
                              void* d_out, int out_size)
{
    (void)in_sizes; (void)n_in; (void)out_size;
    const float* Q  = (const float*)d_in[0];
    const float* K  = (const float*)d_in[1];
    const float* V  = (const float*)d_in[2];
    const float* bq = (const float*)d_in[4];
    const float* bk = (const float*)d_in[6];
    const float* bv = (const float*)d_in[8];
    const float* bo = (const float*)d_in[10];
    float* out = (float*)d_out;

    const int nX4 = MROWS * DM / 4;
    const int nW4 = DM * DM / 4;
    cvt_kernel<<<(nX4 + 255) / 256, 256>>>(Q,                       0, nX4);
    cvt_kernel<<<(nX4 + 255) / 256, 256>>>(K,                       1, nX4);
    cvt_kernel<<<(nX4 + 255) / 256, 256>>>(V,                       2, nX4);
    cvt_kernel<<<(nW4 + 255) / 256, 256>>>((const float*)d_in[3],   3, nW4);
    cvt_kernel<<<(nW4 + 255) / 256, 256>>>((const float*)d_in[5],   4, nW4);
    cvt_kernel<<<(nW4 + 255) / 256, 256>>>((const float*)d_in[7],   5, nW4);
    cvt_kernel<<<(nW4 + 255) / 256, 256>>>((const float*)d_in[9],   6, nW4);

    proj_kernel  <<<dim3(DM / 64, MROWS / 128, 3), 256>>>(bq, bk, bv);
    scores_kernel<<<dim3(S_ / 64, S_ / 128, BH),   256>>>();
    softmax_kernel<<<dim3(BH * S_), 256>>>();
    pv_kernel    <<<dim3(1, S_ / 128, BH),         256>>>();
    out_kernel   <<<dim3(DM / 64, MROWS / 128),    256>>>(out, bo);
}

// round 7
// speedup vs baseline: 2.1849x; 1.2711x over previous
#include <cuda_runtime.h>
#include <cuda_bf16.h>
#include <cstdint>

// ===========================================================================
// MHA  B=2 S=2048 DM=1024 H=16 DK=64 — Round 7:
//   * flash-fused scores+softmax+pv (no g_scores, online softmax)
//   * ldmatrix fragment loads (R3 core, verified bit-identical to PTX tables)
//   * proj / out HMMA split-bf16 as in R6
// C = Ah*Bh + Ah*Bl + Al*Bh, fp32 accumulate.
// ===========================================================================

#define B_    2
#define S_    2048
#define H_    16
#define DK    64
#define DM    1024
#define MROWS (B_ * S_)   // 4096
#define BH    (B_ * H_)   // 32

// ---------------- device scratch ----------------
__device__ __nv_bfloat16 g_Qhi[MROWS * DM], g_Qlo[MROWS * DM];
__device__ __nv_bfloat16 g_Khi[MROWS * DM], g_Klo[MROWS * DM];
__device__ __nv_bfloat16 g_Vhi[MROWS * DM], g_Vlo[MROWS * DM];
__device__ __nv_bfloat16 g_Wqhi[DM * DM], g_Wqlo[DM * DM];
__device__ __nv_bfloat16 g_Wkhi[DM * DM], g_Wklo[DM * DM];
__device__ __nv_bfloat16 g_Wvhi[DM * DM], g_Wvlo[DM * DM];
__device__ __nv_bfloat16 g_Wohi[DM * DM], g_Wolo[DM * DM];
__device__ __nv_bfloat16 g_qhi[BH * S_ * DK], g_qlo[BH * S_ * DK];
__device__ __nv_bfloat16 g_khi[BH * S_ * DK], g_klo[BH * S_ * DK];
__device__ __nv_bfloat16 g_vThi[BH * DK * S_], g_vTlo[BH * DK * S_];
__device__ __nv_bfloat16 g_ctxhi[MROWS * DM], g_ctxlo[MROWS * DM];

// ---------------- helpers ----------------
__device__ __forceinline__ uint32_t smem_u32(const void* p) {
    uint32_t a;
    asm("{ .reg .u64 t; cvta.to.shared.u64 t, %1; cvt.u32.u64 %0, t; }" : "=r"(a) : "l"(p));
    return a;
}
#define SWZ(b) ((b) ^ (((b) >> 3) & 0x70))

__device__ __forceinline__ void ldsm4(uint32_t r[4], uint32_t addr) {
    asm volatile("ldmatrix.sync.aligned.m8n8.x4.shared.b16 {%0,%1,%2,%3}, [%4];"
        : "=r"(r[0]), "=r"(r[1]), "=r"(r[2]), "=r"(r[3]) : "r"(addr));
}
__device__ __forceinline__ void sts128(uint32_t addr, uint4 v) {
    asm volatile("st.shared.v4.b32 [%0], {%1,%2,%3,%4};"
        :: "r"(addr), "r"(v.x), "r"(v.y), "r"(v.z), "r"(v.w) : "memory");
}
__device__ __forceinline__ void sts32(uint32_t addr, uint32_t v) {
    asm volatile("st.shared.b32 [%0], %1;" :: "r"(addr), "r"(v) : "memory");
}
__device__ __forceinline__ void hmma(float c[4], const uint32_t a[4], const uint32_t b[2]) {
    asm volatile("mma.sync.aligned.m16n8k16.row.col.f32.bf16.bf16.f32 "
        "{%0,%1,%2,%3}, {%4,%5,%6,%7}, {%8,%9}, {%0,%1,%2,%3};"
        : "+f"(c[0]), "+f"(c[1]), "+f"(c[2]), "+f"(c[3])
        : "r"(a[0]), "r"(a[1]), "r"(a[2]), "r"(a[3]), "r"(b[0]), "r"(b[1]));
}
__device__ __forceinline__ uint32_t pk2(__nv_bfloat16 a, __nv_bfloat16 b) {
    return (uint32_t)__bfloat16_as_ushort(a) | ((uint32_t)__bfloat16_as_ushort(b) << 16);
}
__device__ __forceinline__ void split2(float x, __nv_bfloat16& h, __nv_bfloat16& l) {
    h = __float2bfloat16(x);
    l = __float2bfloat16(x - __bfloat162float(h));
}

// ---------------------------------------------------------------------------
// One 64-k-deep tile of MMAs: acc(warp 32x32) += A[128x64] * B[64x64]^T
// using ldmatrix fragment loads (verified R3 mapping).
// ---------------------------------------------------------------------------
__device__ __forceinline__ void mma_tile64(
    uint32_t Ab, uint32_t Bb, int rA, int cA, int rB, int cB, float acc[2][4][4])
{
#pragma unroll
    for (int ks = 0; ks < 4; ks++) {
        uint32_t a[2][4], b0[4], b1[4];
        ldsm4(a[0], Ab + SWZ((uint32_t)((rA)      * 128 + cA + ks * 32)));
        ldsm4(a[1], Ab + SWZ((uint32_t)((rA + 16) * 128 + cA + ks * 32)));
        ldsm4(b0,   Bb + SWZ((uint32_t)((rB)      * 128 + cB + ks * 32)));
        ldsm4(b1,   Bb + SWZ((uint32_t)((rB + 16) * 128 + cB + ks * 32)));
        uint32_t bb[4][2] = { {b0[0],b0[1]}, {b0[2],b0[3]},
                              {b1[0],b1[1]}, {b1[2],b1[3]} };
#pragma unroll
        for (int i = 0; i < 2; i++)
#pragma unroll
            for (int j = 0; j < 4; j++)
                hmma(acc[i][j], a[i], bb[j]);
    }
}

// ---------------- proj/out smem tile layout (static 48 KB) ----------------
#define SM_AHI 0
#define SM_ALO 16384
#define SM_BHI 32768
#define SM_BLO 40960
#define SM_SZ  49152

// ---------------------------------------------------------------------------
// GEMM mainloop (proj/out): acc(128x64 block) += 3-pass split MMA over K.
// ---------------------------------------------------------------------------
__device__ __forceinline__ void mma_loop(
    const __nv_bfloat16* __restrict__ Ah, const __nv_bfloat16* __restrict__ Al, int lda,
    const __nv_bfloat16* __restrict__ Bh, const __nv_bfloat16* __restrict__ Bl, int ldb,
    int K, char* sm, float acc[2][4][4])
{
    const int tid  = threadIdx.x;
    const int lane = tid & 31;
    const int wid  = tid >> 5;
    const int wm   = wid >> 1;
    const int wn   = wid & 1;
    const uint32_t smb = smem_u32(sm);

    const int rA = wm * 32 + (lane & 15);
    const int cA = (lane >> 4) << 4;
    const int rB = wn * 32 + (lane & 7) + ((lane & 16) >> 1);
    const int cB = (lane & 8) << 1;

    const int nch = K >> 6;
    for (int ch = 0; ch < nch; ch++) {
        const int k0 = ch << 6;
        __syncthreads();
#pragma unroll
        for (int i = 0; i < 4; i++) {
            int e = (tid + (i << 8)) << 3;
            int row = e >> 6, col = e & 63;
            uint4 uh = *(const uint4*)(Ah + (size_t)row * lda + k0 + col);
            uint4 ul = *(const uint4*)(Al + (size_t)row * lda + k0 + col);
            uint32_t sw = SWZ((uint32_t)(row * 128 + col * 2));
            sts128(smb + SM_AHI + sw, uh);
            sts128(smb + SM_ALO + sw, ul);
        }
#pragma unroll
        for (int i = 0; i < 2; i++) {
            int e = (tid + (i << 8)) << 3;
            int row = e >> 6, col = e & 63;
            uint4 uh = *(const uint4*)(Bh + (size_t)row * ldb + k0 + col);
            uint4 ul = *(const uint4*)(Bl + (size_t)row * ldb + k0 + col);
            uint32_t sw = SWZ((uint32_t)(row * 128 + col * 2));
            sts128(smb + SM_BHI + sw, uh);
            sts128(smb + SM_BLO + sw, ul);
        }
        __syncthreads();
#pragma unroll
        for (int p = 0; p < 3; p++) {
            const uint32_t Ab = smb + ((p == 2) ? SM_ALO : SM_AHI);
            const uint32_t Bb = smb + ((p == 1) ? SM_BLO : SM_BHI);
            mma_tile64(Ab, Bb, rA, cA, rB, cB, acc);
        }
    }
}

// ---------------------------------------------------------------------------
// cvt: fp32 -> (hi, lo) bf16. Destinations resolved inside device code.
// ---------------------------------------------------------------------------
__global__ void cvt_kernel(const float* __restrict__ src, int which, int n4)
{
    int i = blockIdx.x * blockDim.x + threadIdx.x;
    if (i >= n4) return;

    __nv_bfloat16 *hi, *lo;
    switch (which) {
        case 0: hi = g_Qhi;  lo = g_Qlo;  break;
        case 1: hi = g_Khi;  lo = g_Klo;  break;
        case 2: hi = g_Vhi;  lo = g_Vlo;  break;
        case 3: hi = g_Wqhi; lo = g_Wqlo; break;
        case 4: hi = g_Wkhi; lo = g_Wklo; break;
        case 5: hi = g_Wvhi; lo = g_Wvlo; break;
        default: hi = g_Wohi; lo = g_Wolo; break;
    }

    float4 v = ((const float4*)src)[i];
    __nv_bfloat16 h[4], l[4];
    split2(v.x, h[0], l[0]); split2(v.y, h[1], l[1]);
    split2(v.z, h[2], l[2]); split2(v.w, h[3], l[3]);
    uint2 uh = { pk2(h[0], h[1]), pk2(h[2], h[3]) };
    uint2 ul = { pk2(l[0], l[1]), pk2(l[2], l[3]) };
    ((uint2*)hi)[i] = uh;
    ((uint2*)lo)[i] = ul;
}

// ---------------------------------------------------------------------------
// proj: z in {0,1,2} -> q, k (head-split), vT (transposed). grid (16, 32, 3)
// ---------------------------------------------------------------------------
__global__ __launch_bounds__(256) void proj_kernel(
    const float* __restrict__ bq, const float* __restrict__ bk,
    const float* __restrict__ bv)
{
    __shared__ char sm[SM_SZ];
    const int z  = blockIdx.z;
    const int n0 = blockIdx.x * 64;
    const int m0 = blockIdx.y * 128;

    const __nv_bfloat16 *Ah, *Al, *Bh, *Bl;
    const float* bias;
    if (z == 0)      { Ah = g_Qhi; Al = g_Qlo; Bh = g_Wqhi; Bl = g_Wqlo; bias = bq; }
    else if (z == 1) { Ah = g_Khi; Al = g_Klo; Bh = g_Wkhi; Bl = g_Wklo; bias = bk; }
    else             { Ah = g_Vhi; Al = g_Vlo; Bh = g_Wvhi; Bl = g_Wvlo; bias = bv; }

    float acc[2][4][4];
#pragma unroll
    for (int i = 0; i < 2; i++)
#pragma unroll
        for (int j = 0; j < 4; j++)
#pragma unroll
            for (int q = 0; q < 4; q++) acc[i][j][q] = 0.f;

    mma_loop(Ah + (size_t)m0 * DM, Al + (size_t)m0 * DM, DM,
             Bh + (size_t)n0 * DM, Bl + (size_t)n0 * DM, DM, DM, sm, acc);

    const int lane = threadIdx.x & 31, wid = threadIdx.x >> 5;
    const int wm = wid >> 1, wn = wid & 1;
#pragma unroll
    for (int i = 0; i < 2; i++)
#pragma unroll
    for (int half = 0; half < 2; half++) {
        const int r = m0 + wm * 32 + i * 16 + (lane >> 2) + half * 8;
        const int b = r >> 11, s = r & (S_ - 1);
#pragma unroll
        for (int j = 0; j < 4; j++)
#pragma unroll
        for (int q = 0; q < 2; q++) {
            const int n = n0 + wn * 32 + j * 8 + 2 * (lane & 3) + q;
            float v = acc[i][j][half * 2 + q] + bias[n];
            __nv_bfloat16 h, l; split2(v, h, l);
            const int hh = n >> 6, dk = n & 63;
            const size_t bh = (size_t)(b * H_ + hh);
            if (z == 0) {
                g_qhi[(bh * S_ + s) * DK + dk] = h;
                g_qlo[(bh * S_ + s) * DK + dk] = l;
            } else if (z == 1) {
                g_khi[(bh * S_ + s) * DK + dk] = h;
                g_klo[(bh * S_ + s) * DK + dk] = l;
            } else {
                g_vThi[(bh * DK + dk) * S_ + s] = h;
                g_vTlo[(bh * DK + dk) * S_ + s] = l;
            }
        }
    }
}

// ---------------- flash smem layout (dynamic, ~82 KB) ----------------
#define FL_QHI   0
#define FL_QLO   16384
#define FL_KVHI  32768
#define FL_KVLO  40960
#define FL_PHI   49152
#define FL_PLO   65536
#define FL_MAXST 81920                 // float [2][128]
#define FL_SUMST (81920 + 1024)       // float [2][128]
#define FL_SZ    (81920 + 2048)

// ---------------------------------------------------------------------------
// flash: fused scores+softmax+pv for one (bh, 128-row q tile). grid (16, BH)
// ---------------------------------------------------------------------------
__global__ __launch_bounds__(256) void flash_kernel()
{
    extern __shared__ char sm[];
    const uint32_t smb = smem_u32(sm);

    const int bh = blockIdx.y;
    const int m0 = blockIdx.x * 128;
    const size_t qoff = (size_t)bh * S_ * DK;
    const size_t voff = (size_t)bh * DK * S_;

    const int tid  = threadIdx.x;
    const int lane = tid & 31;
    const int wid  = tid >> 5;
    const int wm   = wid >> 1;
    const int wn   = wid & 1;
    const int g    = lane >> 2;
    const int tq   = lane & 3;

    const int rA = wm * 32 + (lane & 15);
    const int cA = (lane >> 4) << 4;
    const int rB = wn * 32 + (lane & 7) + ((lane & 16) >> 1);
    const int cB = (lane & 8) << 1;

    // ---- load Q tile (persistent) ----
#pragma unroll
    for (int i = 0; i < 4; i++) {
        int e = (tid + (i << 8)) << 3;
        int row = e >> 6, col = e & 63;
        uint4 uh = *(const uint4*)(g_qhi + qoff + (size_t)(m0 + row) * DK + col);
        uint4 ul = *(const uint4*)(g_qlo + qoff + (size_t)(m0 + row) * DK + col);
        uint32_t sw = SWZ((uint32_t)(row * 128 + col * 2));
        sts128(smb + FL_QHI + sw, uh);
        sts128(smb + FL_QLO + sw, ul);
    }

    float acc_o[2][4][4];
#pragma unroll
    for (int i = 0; i < 2; i++)
#pragma unroll
        for (int j = 0; j < 4; j++)
#pragma unroll
            for (int q = 0; q < 4; q++) acc_o[i][j][q] = 0.f;
    float mrow[2][2] = { {-1e30f, -1e30f}, {-1e30f, -1e30f} };
    float srow[2][2] = { {0.f, 0.f}, {0.f, 0.f} };

    for (int n0 = 0; n0 < S_; n0 += 64) {
        __syncthreads();   // previous chunk's PV reads of P/KV done; Q load done (chunk 0)

        // ---- fill K chunk (64 x 64) hi/lo ----
#pragma unroll
        for (int i = 0; i < 2; i++) {
            int e = (tid + (i << 8)) << 3;
            int row = e >> 6, col = e & 63;
            uint4 uh = *(const uint4*)(g_khi + qoff + (size_t)(n0 + row) * DK + col);
            uint4 ul = *(const uint4*)(g_klo + qoff + (size_t)(n0 + row) * DK + col);
            uint32_t sw = SWZ((uint32_t)(row * 128 + col * 2));
            sts128(smb + FL_KVHI + sw, uh);
            sts128(smb + FL_KVLO + sw, ul);
        }
        __syncthreads();

        // ---- S = q k^T (split, scaled) ----
        float s[2][4][4];
#pragma unroll
        for (int i = 0; i < 2; i++)
#pragma unroll
            for (int j = 0; j < 4; j++)
#pragma unroll
                for (int q = 0; q < 4; q++) s[i][j][q] = 0.f;
#pragma unroll
        for (int p = 0; p < 3; p++) {
            const uint32_t Ab = smb + ((p == 2) ? FL_QLO : FL_QHI);
            const uint32_t Bb = smb + ((p == 1) ? FL_KVLO : FL_KVHI);
            mma_tile64(Ab, Bb, rA, cA, rB, cB, s);
        }
#pragma unroll
        for (int i = 0; i < 2; i++)
#pragma unroll
            for (int j = 0; j < 4; j++)
#pragma unroll
                for (int q = 0; q < 4; q++) s[i][j][q] *= 0.125f;

        // ---- per-row chunk max (quad shuffle + stage) ----
#pragma unroll
        for (int i = 0; i < 2; i++)
#pragma unroll
        for (int half = 0; half < 2; half++) {
            float mx = -1e30f;
#pragma unroll
            for (int j = 0; j < 4; j++) {
                mx = fmaxf(mx, s[i][j][half * 2]);
                mx = fmaxf(mx, s[i][j][half * 2 + 1]);
            }
            mx = fmaxf(mx, __shfl_xor_sync(~0u, mx, 1));
            mx = fmaxf(mx, __shfl_xor_sync(~0u, mx, 2));
            const int rl = wm * 32 + i * 16 + half * 8 + g;
            if (tq == 0) sts32(smb + FL_MAXST + (wn * 128 + rl) * 4, __float_as_uint(mx));
        }
        __syncthreads();

        // ---- online update: m, p = exp(s-m), partial sums, rescale O, write P ----
        const float* maxst = (const float*)(sm + FL_MAXST);
#pragma unroll
        for (int i = 0; i < 2; i++)
#pragma unroll
        for (int half = 0; half < 2; half++) {
            const int rl = wm * 32 + i * 16 + half * 8 + g;
            const float cm = fmaxf(maxst[rl], maxst[128 + rl]);
            const float mn = fmaxf(mrow[i][half], cm);
            const float alpha = __expf(mrow[i][half] - mn);
            mrow[i][half] = mn;
            srow[i][half] *= alpha;

            float ps = 0.f;
#pragma unroll
            for (int j = 0; j < 4; j++) {
                float p0 = __expf(s[i][j][half * 2]     - mn);
                float p1 = __expf(s[i][j][half * 2 + 1] - mn);
                ps += p0 + p1;
                // write P hi/lo (bf16x2) at (rl, key col)
                __nv_bfloat16 h0, l0, h1, l1;
                split2(p0, h0, l0); split2(p1, h1, l1);
                const int c = wn * 32 + j * 8 + 2 * tq;
                const uint32_t sw = SWZ((uint32_t)(rl * 128 + c * 2));
                sts32(smb + FL_PHI + sw, pk2(h0, h1));
                sts32(smb + FL_PLO + sw, pk2(l0, l1));
                // rescale O accumulators
                acc_o[i][j][half * 2]     *= alpha;
                acc_o[i][j][half * 2 + 1] *= alpha;
            }
            ps += __shfl_xor_sync(~0u, ps, 1);
            ps += __shfl_xor_sync(~0u, ps, 2);
            if (tq == 0) sts32(smb + FL_SUMST + (wn * 128 + rl) * 4, __float_as_uint(ps));
        }
        __syncthreads();

        // ---- accumulate row sums; fill V chunk (vT: rows=dk, cols=keys) ----
        const float* sumst = (const float*)(sm + FL_SUMST);
#pragma unroll
        for (int i = 0; i < 2; i++)
#pragma unroll
        for (int half = 0; half < 2; half++) {
            const int rl = wm * 32 + i * 16 + half * 8 + g;
            srow[i][half] += sumst[rl] + sumst[128 + rl];
        }
#pragma unroll
        for (int i = 0; i < 2; i++) {
            int e = (tid + (i << 8)) << 3;
            int row = e >> 6, col = e & 63;     // row = dk, col = key
            uint4 uh = *(const uint4*)(g_vThi + voff + (size_t)row * S_ + n0 + col);
            uint4 ul = *(const uint4*)(g_vTlo + voff + (size_t)row * S_ + n0 + col);
            uint32_t sw = SWZ((uint32_t)(row * 128 + col * 2));
            sts128(smb + FL_KVHI + sw, uh);
            sts128(smb + FL_KVLO + sw, ul);
        }
        __syncthreads();

        // ---- O += P @ V (split) ----
#pragma unroll
        for (int p = 0; p < 3; p++) {
            const uint32_t Ab = smb + ((p == 2) ? FL_PLO : FL_PHI);
            const uint32_t Bb = smb + ((p == 1) ? FL_KVLO : FL_KVHI);
            mma_tile64(Ab, Bb, rA, cA, rB, cB, acc_o);
        }
    }

    // ---- epilogue: normalize, split, write ctx ----
    const int b = bh >> 4, h = bh & 15;
#pragma unroll
    for (int i = 0; i < 2; i++)
#pragma unroll
    for (int half = 0; half < 2; half++) {
        const int r = m0 + wm * 32 + i * 16 + g + half * 8;
        const float inv = 1.0f / srow[i][half];
        const size_t rowoff = ((size_t)(b * S_ + r)) * DM + h * DK;
#pragma unroll
        for (int j = 0; j < 4; j++)
#pragma unroll
        for (int q = 0; q < 2; q++) {
            const int d = wn * 32 + j * 8 + 2 * tq + q;
            __nv_bfloat16 hh, ll; split2(acc_o[i][j][half * 2 + q] * inv, hh, ll);
            g_ctxhi[rowoff + d] = hh;
            g_ctxlo[rowoff + d] = ll;
        }
    }
}

// ---------------------------------------------------------------------------
// out: out = ctx @ Wo^T + bo.  grid (16, 32)
// ---------------------------------------------------------------------------
__global__ __launch_bounds__(256) void out_kernel(float* __restrict__ out,
                                                  const float* __restrict__ bo)
{
    __shared__ char sm[SM_SZ];
    const int n0 = blockIdx.x * 64;
    const int m0 = blockIdx.y * 128;

    float acc[2][4][4];
#pragma unroll
    for (int i = 0; i < 2; i++)
#pragma unroll
        for (int j = 0; j < 4; j++)
#pragma unroll
            for (int q = 0; q < 4; q++) acc[i][j][q] = 0.f;

    mma_loop(g_ctxhi + (size_t)m0 * DM, g_ctxlo + (size_t)m0 * DM, DM,
             g_Wohi + (size_t)n0 * DM, g_Wolo + (size_t)n0 * DM, DM, DM, sm, acc);

    const int lane = threadIdx.x & 31, wid = threadIdx.x >> 5;
    const int wm = wid >> 1, wn = wid & 1;
#pragma unroll
    for (int i = 0; i < 2; i++)
#pragma unroll
    for (int half = 0; half < 2; half++) {
        const int r = m0 + wm * 32 + i * 16 + (lane >> 2) + half * 8;
#pragma unroll
        for (int j = 0; j < 4; j++) {
            const int c = n0 + wn * 32 + j * 8 + 2 * (lane & 3);
            float2 o = { acc[i][j][half * 2] + bo[c],
                         acc[i][j][half * 2 + 1] + bo[c + 1] };
            *(float2*)(out + (size_t)r * DM + c) = o;
        }
    }
}

// ---------------------------------------------------------------------------
// launcher — no __device__ symbol referenced from host code.
// ---------------------------------------------------------------------------
extern "C" void kernel_launch(void* const* d_in, const int* in_sizes, int n_in,
                              void* d_out, int out_size)
{
    (void)in_sizes; (void)n_in; (void)out_size;
    const float* Q  = (const float*)d_in[0];
    const float* K  = (const float*)d_in[1];
    const float* V  = (const float*)d_in[2];
    const float* bq = (const float*)d_in[4];
    const float* bk = (const float*)d_in[6];
    const float* bv = (const float*)d_in[8];
    const float* bo = (const float*)d_in[10];
    float* out = (float*)d_out;

    cudaFuncSetAttribute(flash_kernel, cudaFuncAttributeMaxDynamicSharedMemorySize, FL_SZ);

    const int nX4 = MROWS * DM / 4;
    const int nW4 = DM * DM / 4;
    cvt_kernel<<<(nX4 + 255) / 256, 256>>>(Q,                     0, nX4);
    cvt_kernel<<<(nX4 + 255) / 256, 256>>>(K,                     1, nX4);
    cvt_kernel<<<(nX4 + 255) / 256, 256>>>(V,                     2, nX4);
    cvt_kernel<<<(nW4 + 255) / 256, 256>>>((const float*)d_in[3], 3, nW4);
    cvt_kernel<<<(nW4 + 255) / 256, 256>>>((const float*)d_in[5], 4, nW4);
    cvt_kernel<<<(nW4 + 255) / 256, 256>>>((const float*)d_in[7], 5, nW4);
    cvt_kernel<<<(nW4 + 255) / 256, 256>>>((const float*)d_in[9], 6, nW4);

    proj_kernel <<<dim3(DM / 64, MROWS / 128, 3), 256>>>(bq, bk, bv);
    flash_kernel<<<dim3(S_ / 128, BH), 256, FL_SZ>>>();
    out_kernel  <<<dim3(DM / 64, MROWS / 128),    256>>>(out, bo);
}

// round 8
// speedup vs baseline: 2.9139x; 1.3336x over previous
#include <cuda_runtime.h>
#include <cuda_bf16.h>
#include <cstdint>

// ===========================================================================
// MHA  B=2 S=2048 DM=1024 H=16 DK=64 — Round 8:
//   cp.async double-buffered mainloops (proj/out) + pipelined flash K/V loads
//   ldmatrix fragments, split-bf16 HMMA (C = Ah*Bh + Ah*Bl + Al*Bh).
// ===========================================================================

#define B_    2
#define S_    2048
#define H_    16
#define DK    64
#define DM    1024
#define MROWS (B_ * S_)   // 4096
#define BH    (B_ * H_)   // 32

// ---------------- device scratch ----------------
__device__ __nv_bfloat16 g_Qhi[MROWS * DM], g_Qlo[MROWS * DM];
__device__ __nv_bfloat16 g_Khi[MROWS * DM], g_Klo[MROWS * DM];
__device__ __nv_bfloat16 g_Vhi[MROWS * DM], g_Vlo[MROWS * DM];
__device__ __nv_bfloat16 g_Wqhi[DM * DM], g_Wqlo[DM * DM];
__device__ __nv_bfloat16 g_Wkhi[DM * DM], g_Wklo[DM * DM];
__device__ __nv_bfloat16 g_Wvhi[DM * DM], g_Wvlo[DM * DM];
__device__ __nv_bfloat16 g_Wohi[DM * DM], g_Wolo[DM * DM];
__device__ __nv_bfloat16 g_qhi[BH * S_ * DK], g_qlo[BH * S_ * DK];
__device__ __nv_bfloat16 g_khi[BH * S_ * DK], g_klo[BH * S_ * DK];
__device__ __nv_bfloat16 g_vThi[BH * DK * S_], g_vTlo[BH * DK * S_];
__device__ __nv_bfloat16 g_ctxhi[MROWS * DM], g_ctxlo[MROWS * DM];

// ---------------- helpers ----------------
__device__ __forceinline__ uint32_t smem_u32(const void* p) {
    uint32_t a;
    asm("{ .reg .u64 t; cvta.to.shared.u64 t, %1; cvt.u32.u64 %0, t; }" : "=r"(a) : "l"(p));
    return a;
}
#define SWZ(b) ((b) ^ (((b) >> 3) & 0x70))

__device__ __forceinline__ void ldsm4(uint32_t r[4], uint32_t addr) {
    asm volatile("ldmatrix.sync.aligned.m8n8.x4.shared.b16 {%0,%1,%2,%3}, [%4];"
        : "=r"(r[0]), "=r"(r[1]), "=r"(r[2]), "=r"(r[3]) : "r"(addr));
}
__device__ __forceinline__ void sts32(uint32_t addr, uint32_t v) {
    asm volatile("st.shared.b32 [%0], %1;" :: "r"(addr), "r"(v) : "memory");
}
__device__ __forceinline__ void cpa16(uint32_t dst, const void* src) {
    asm volatile("cp.async.cg.shared.global [%0], [%1], 16;" :: "r"(dst), "l"(src) : "memory");
}
#define CP_COMMIT() asm volatile("cp.async.commit_group;" ::: "memory")
#define CP_WAIT0()  asm volatile("cp.async.wait_group 0;" ::: "memory")

__device__ __forceinline__ void hmma(float c[4], const uint32_t a[4], const uint32_t b[2]) {
    asm volatile("mma.sync.aligned.m16n8k16.row.col.f32.bf16.bf16.f32 "
        "{%0,%1,%2,%3}, {%4,%5,%6,%7}, {%8,%9}, {%0,%1,%2,%3};"
        : "+f"(c[0]), "+f"(c[1]), "+f"(c[2]), "+f"(c[3])
        : "r"(a[0]), "r"(a[1]), "r"(a[2]), "r"(a[3]), "r"(b[0]), "r"(b[1]));
}
__device__ __forceinline__ uint32_t pk2(__nv_bfloat16 a, __nv_bfloat16 b) {
    return (uint32_t)__bfloat16_as_ushort(a) | ((uint32_t)__bfloat16_as_ushort(b) << 16);
}
__device__ __forceinline__ void split2(float x, __nv_bfloat16& h, __nv_bfloat16& l) {
    h = __float2bfloat16(x);
    l = __float2bfloat16(x - __bfloat162float(h));
}

// ---------------------------------------------------------------------------
// One 64-k-deep tile of MMAs: acc(warp 32x32) += A[128x64] * B[64x64]^T
// ---------------------------------------------------------------------------
__device__ __forceinline__ void mma_tile64(
    uint32_t Ab, uint32_t Bb, int rA, int cA, int rB, int cB, float acc[2][4][4])
{
#pragma unroll
    for (int ks = 0; ks < 4; ks++) {
        uint32_t a[2][4], b0[4], b1[4];
        ldsm4(a[0], Ab + SWZ((uint32_t)((rA)      * 128 + cA + ks * 32)));
        ldsm4(a[1], Ab + SWZ((uint32_t)((rA + 16) * 128 + cA + ks * 32)));
        ldsm4(b0,   Bb + SWZ((uint32_t)((rB)      * 128 + cB + ks * 32)));
        ldsm4(b1,   Bb + SWZ((uint32_t)((rB + 16) * 128 + cB + ks * 32)));
        uint32_t bb[4][2] = { {b0[0],b0[1]}, {b0[2],b0[3]},
                              {b1[0],b1[1]}, {b1[2],b1[3]} };
#pragma unroll
        for (int i = 0; i < 2; i++)
#pragma unroll
            for (int j = 0; j < 4; j++)
                hmma(acc[i][j], a[i], bb[j]);
    }
}

// ---------------- proj/out pipelined smem: 2 stages x 48 KB ----------------
#define STG_AHI 0
#define STG_ALO 16384
#define STG_BHI 32768
#define STG_BLO 40960
#define STG_SZ  49152
#define GE_SZ   (2 * STG_SZ)   // 96 KB dynamic

// ---------------------------------------------------------------------------
// GEMM mainloop (proj/out): 2-stage cp.async pipeline, 3-pass split MMA.
// ---------------------------------------------------------------------------
__device__ __forceinline__ void mma_loop(
    const __nv_bfloat16* __restrict__ Ah, const __nv_bfloat16* __restrict__ Al, int lda,
    const __nv_bfloat16* __restrict__ Bh, const __nv_bfloat16* __restrict__ Bl, int ldb,
    int K, char* sm, float acc[2][4][4])
{
    const int tid  = threadIdx.x;
    const int lane = tid & 31;
    const int wid  = tid >> 5;
    const int wm   = wid >> 1;
    const int wn   = wid & 1;
    const uint32_t smb = smem_u32(sm);

    const int rA = wm * 32 + (lane & 15);
    const int cA = (lane >> 4) << 4;
    const int rB = wn * 32 + (lane & 7) + ((lane & 16) >> 1);
    const int cB = (lane & 8) << 1;

    auto issue = [&](int ch, uint32_t st) {
        const int k0 = ch << 6;
#pragma unroll
        for (int i = 0; i < 4; i++) {
            int e = (tid + (i << 8)) << 3;
            int row = e >> 6, col = e & 63;
            uint32_t sw = SWZ((uint32_t)(row * 128 + col * 2));
            cpa16(st + STG_AHI + sw, Ah + (size_t)row * lda + k0 + col);
            cpa16(st + STG_ALO + sw, Al + (size_t)row * lda + k0 + col);
        }
#pragma unroll
        for (int i = 0; i < 2; i++) {
            int e = (tid + (i << 8)) << 3;
            int row = e >> 6, col = e & 63;
            uint32_t sw = SWZ((uint32_t)(row * 128 + col * 2));
            cpa16(st + STG_BHI + sw, Bh + (size_t)row * ldb + k0 + col);
            cpa16(st + STG_BLO + sw, Bl + (size_t)row * ldb + k0 + col);
        }
    };

    const int nch = K >> 6;
    issue(0, smb); CP_COMMIT();
    for (int ch = 0; ch < nch; ch++) {
        CP_WAIT0();
        __syncthreads();
        if (ch + 1 < nch) { issue(ch + 1, smb + ((ch + 1) & 1) * STG_SZ); CP_COMMIT(); }
        const uint32_t st = smb + (ch & 1) * STG_SZ;
#pragma unroll
        for (int p = 0; p < 3; p++) {
            const uint32_t Ab = st + ((p == 2) ? STG_ALO : STG_AHI);
            const uint32_t Bb = st + ((p == 1) ? STG_BLO : STG_BHI);
            mma_tile64(Ab, Bb, rA, cA, rB, cB, acc);
        }
    }
}

// ---------------------------------------------------------------------------
// cvt: fp32 -> (hi, lo) bf16. Destinations resolved inside device code.
// ---------------------------------------------------------------------------
__global__ void cvt_kernel(const float* __restrict__ src, int which, int n4)
{
    int i = blockIdx.x * blockDim.x + threadIdx.x;
    if (i >= n4) return;

    __nv_bfloat16 *hi, *lo;
    switch (which) {
        case 0: hi = g_Qhi;  lo = g_Qlo;  break;
        case 1: hi = g_Khi;  lo = g_Klo;  break;
        case 2: hi = g_Vhi;  lo = g_Vlo;  break;
        case 3: hi = g_Wqhi; lo = g_Wqlo; break;
        case 4: hi = g_Wkhi; lo = g_Wklo; break;
        case 5: hi = g_Wvhi; lo = g_Wvlo; break;
        default: hi = g_Wohi; lo = g_Wolo; break;
    }

    float4 v = ((const float4*)src)[i];
    __nv_bfloat16 h[4], l[4];
    split2(v.x, h[0], l[0]); split2(v.y, h[1], l[1]);
    split2(v.z, h[2], l[2]); split2(v.w, h[3], l[3]);
    uint2 uh = { pk2(h[0], h[1]), pk2(h[2], h[3]) };
    uint2 ul = { pk2(l[0], l[1]), pk2(l[2], l[3]) };
    ((uint2*)hi)[i] = uh;
    ((uint2*)lo)[i] = ul;
}

// ---------------------------------------------------------------------------
// proj: z in {0,1,2} -> q (pre-scaled by 0.125), k, vT. grid (16, 32, 3)
// ---------------------------------------------------------------------------
__global__ __launch_bounds__(256) void proj_kernel(
    const float* __restrict__ bq, const float* __restrict__ bk,
    const float* __restrict__ bv)
{
    extern __shared__ char sm[];
    const int z  = blockIdx.z;
    const int n0 = blockIdx.x * 64;
    const int m0 = blockIdx.y * 128;

    const __nv_bfloat16 *Ah, *Al, *Bh, *Bl;
    const float* bias;
    if (z == 0)      { Ah = g_Qhi; Al = g_Qlo; Bh = g_Wqhi; Bl = g_Wqlo; bias = bq; }
    else if (z == 1) { Ah = g_Khi; Al = g_Klo; Bh = g_Wkhi; Bl = g_Wklo; bias = bk; }
    else             { Ah = g_Vhi; Al = g_Vlo; Bh = g_Wvhi; Bl = g_Wvlo; bias = bv; }

    float acc[2][4][4];
#pragma unroll
    for (int i = 0; i < 2; i++)
#pragma unroll
        for (int j = 0; j < 4; j++)
#pragma unroll
            for (int q = 0; q < 4; q++) acc[i][j][q] = 0.f;

    mma_loop(Ah + (size_t)m0 * DM, Al + (size_t)m0 * DM, DM,
             Bh + (size_t)n0 * DM, Bl + (size_t)n0 * DM, DM, DM, sm, acc);

    const int lane = threadIdx.x & 31, wid = threadIdx.x >> 5;
    const int wm = wid >> 1, wn = wid & 1;
#pragma unroll
    for (int i = 0; i < 2; i++)
#pragma unroll
    for (int half = 0; half < 2; half++) {
        const int r = m0 + wm * 32 + i * 16 + (lane >> 2) + half * 8;
        const int b = r >> 11, s = r & (S_ - 1);
#pragma unroll
        for (int j = 0; j < 4; j++)
#pragma unroll
        for (int q = 0; q < 2; q++) {
            const int n = n0 + wn * 32 + j * 8 + 2 * (lane & 3) + q;
            float v = acc[i][j][half * 2 + q] + bias[n];
            if (z == 0) v *= 0.125f;                 // fold softmax scale into q
            __nv_bfloat16 h, l; split2(v, h, l);
            const int hh = n >> 6, dk = n & 63;
            const size_t bh = (size_t)(b * H_ + hh);
            if (z == 0) {
                g_qhi[(bh * S_ + s) * DK + dk] = h;
                g_qlo[(bh * S_ + s) * DK + dk] = l;
            } else if (z == 1) {
                g_khi[(bh * S_ + s) * DK + dk] = h;
                g_klo[(bh * S_ + s) * DK + dk] = l;
            } else {
                g_vThi[(bh * DK + dk) * S_ + s] = h;
                g_vTlo[(bh * DK + dk) * S_ + s] = l;
            }
        }
    }
}

// ---------------- flash smem layout (dynamic, 98 KB + staging) ----------------
#define FL_QHI 0
#define FL_QLO 16384
#define FL_KA  32768            // K buffer: hi @ +0 (8K), lo @ +8192
#define FL_KB  49152            // V buffer: hi @ +0 (8K), lo @ +8192
#define FL_PHI 65536
#define FL_PLO 81920
#define FL_MAX 98304            // float [2][128]
#define FL_SUM 99328            // float [2][128]
#define FL_SZ  100352

// ---------------------------------------------------------------------------
// flash: fused scores+softmax+pv, cp.async pipelined. grid (16, BH)
// ---------------------------------------------------------------------------
__global__ __launch_bounds__(256) void flash_kernel()
{
    extern __shared__ char sm[];
    const uint32_t smb = smem_u32(sm);

    const int bh = blockIdx.y;
    const int m0 = blockIdx.x * 128;
    const size_t qoff = (size_t)bh * S_ * DK;
    const size_t voff = (size_t)bh * DK * S_;

    const int tid  = threadIdx.x;
    const int lane = tid & 31;
    const int wid  = tid >> 5;
    const int wm   = wid >> 1;
    const int wn   = wid & 1;
    const int g    = lane >> 2;
    const int tq   = lane & 3;

    const int rA = wm * 32 + (lane & 15);
    const int cA = (lane >> 4) << 4;
    const int rB = wn * 32 + (lane & 7) + ((lane & 16) >> 1);
    const int cB = (lane & 8) << 1;

    auto issueK = [&](int n0) {
#pragma unroll
        for (int i = 0; i < 2; i++) {
            int e = (tid + (i << 8)) << 3;
            int row = e >> 6, col = e & 63;
            uint32_t sw = SWZ((uint32_t)(row * 128 + col * 2));
            cpa16(smb + FL_KA + sw,        g_khi + qoff + (size_t)(n0 + row) * DK + col);
            cpa16(smb + FL_KA + 8192 + sw, g_klo + qoff + (size_t)(n0 + row) * DK + col);
        }
    };
    auto issueV = [&](int n0) {
#pragma unroll
        for (int i = 0; i < 2; i++) {
            int e = (tid + (i << 8)) << 3;
            int row = e >> 6, col = e & 63;     // row = dk, col = key
            uint32_t sw = SWZ((uint32_t)(row * 128 + col * 2));
            cpa16(smb + FL_KB + sw,        g_vThi + voff + (size_t)row * S_ + n0 + col);
            cpa16(smb + FL_KB + 8192 + sw, g_vTlo + voff + (size_t)row * S_ + n0 + col);
        }
    };

    // ---- issue Q (persistent) + K chunk 0, one group ----
#pragma unroll
    for (int i = 0; i < 4; i++) {
        int e = (tid + (i << 8)) << 3;
        int row = e >> 6, col = e & 63;
        uint32_t sw = SWZ((uint32_t)(row * 128 + col * 2));
        cpa16(smb + FL_QHI + sw, g_qhi + qoff + (size_t)(m0 + row) * DK + col);
        cpa16(smb + FL_QLO + sw, g_qlo + qoff + (size_t)(m0 + row) * DK + col);
    }
    issueK(0);
    CP_COMMIT();

    float acc_o[2][4][4];
#pragma unroll
    for (int i = 0; i < 2; i++)
#pragma unroll
        for (int j = 0; j < 4; j++)
#pragma unroll
            for (int q = 0; q < 4; q++) acc_o[i][j][q] = 0.f;
    float mrow[2][2] = { {-1e30f, -1e30f}, {-1e30f, -1e30f} };
    float srow[2][2] = { {0.f, 0.f}, {0.f, 0.f} };

    for (int ch = 0; ch < S_ / 64; ch++) {
        const int n0 = ch << 6;

        CP_WAIT0();
        __syncthreads();                 // K(ch) visible; all warps done with V(ch-1)
        issueV(n0); CP_COMMIT();         // V(ch) flies during S-mma + softmax

        // ---- S = q k^T (q pre-scaled) ----
        float s[2][4][4];
#pragma unroll
        for (int i = 0; i < 2; i++)
#pragma unroll
            for (int j = 0; j < 4; j++)
#pragma unroll
                for (int q = 0; q < 4; q++) s[i][j][q] = 0.f;
#pragma unroll
        for (int p = 0; p < 3; p++) {
            const uint32_t Ab = smb + ((p == 2) ? FL_QLO : FL_QHI);
            const uint32_t Bb = smb + FL_KA + ((p == 1) ? 8192 : 0);
            mma_tile64(Ab, Bb, rA, cA, rB, cB, s);
        }

        // ---- per-row chunk max (quad shuffle + cross-warp stage) ----
#pragma unroll
        for (int i = 0; i < 2; i++)
#pragma unroll
        for (int half = 0; half < 2; half++) {
            float mx = -1e30f;
#pragma unroll
            for (int j = 0; j < 4; j++) {
                mx = fmaxf(mx, s[i][j][half * 2]);
                mx = fmaxf(mx, s[i][j][half * 2 + 1]);
            }
            mx = fmaxf(mx, __shfl_xor_sync(~0u, mx, 1));
            mx = fmaxf(mx, __shfl_xor_sync(~0u, mx, 2));
            const int rl = wm * 32 + i * 16 + half * 8 + g;
            if (tq == 0) sts32(smb + FL_MAX + (wn * 128 + rl) * 4, __float_as_uint(mx));
        }
        __syncthreads();

        // ---- online update: m, p, P write, partial sums, O rescale ----
        const float* maxst = (const float*)(sm + FL_MAX);
#pragma unroll
        for (int i = 0; i < 2; i++)
#pragma unroll
        for (int half = 0; half < 2; half++) {
            const int rl = wm * 32 + i * 16 + half * 8 + g;
            const float cm = fmaxf(maxst[rl], maxst[128 + rl]);
            const float mn = fmaxf(mrow[i][half], cm);
            const float alpha = __expf(mrow[i][half] - mn);
            mrow[i][half] = mn;
            srow[i][half] *= alpha;

            float ps = 0.f;
#pragma unroll
            for (int j = 0; j < 4; j++) {
                float p0 = __expf(s[i][j][half * 2]     - mn);
                float p1 = __expf(s[i][j][half * 2 + 1] - mn);
                ps += p0 + p1;
                __nv_bfloat16 h0, l0, h1, l1;
                split2(p0, h0, l0); split2(p1, h1, l1);
                const int c = wn * 32 + j * 8 + 2 * tq;
                const uint32_t sw = SWZ((uint32_t)(rl * 128 + c * 2));
                sts32(smb + FL_PHI + sw, pk2(h0, h1));
                sts32(smb + FL_PLO + sw, pk2(l0, l1));
                acc_o[i][j][half * 2]     *= alpha;
                acc_o[i][j][half * 2 + 1] *= alpha;
            }
            ps += __shfl_xor_sync(~0u, ps, 1);
            ps += __shfl_xor_sync(~0u, ps, 2);
            if (tq == 0) sts32(smb + FL_SUM + (wn * 128 + rl) * 4, __float_as_uint(ps));
        }

        CP_WAIT0();
        __syncthreads();                 // V(ch) + P + sums visible; S-mma done with K buf
        if (ch + 1 < S_ / 64) { issueK(n0 + 64); CP_COMMIT(); }  // K(ch+1) flies during PV

        const float* sumst = (const float*)(sm + FL_SUM);
#pragma unroll
        for (int i = 0; i < 2; i++)
#pragma unroll
        for (int half = 0; half < 2; half++) {
            const int rl = wm * 32 + i * 16 + half * 8 + g;
            srow[i][half] += sumst[rl] + sumst[128 + rl];
        }

        // ---- O += P @ V ----
#pragma unroll
        for (int p = 0; p < 3; p++) {
            const uint32_t Ab = smb + ((p == 2) ? FL_PLO : FL_PHI);
            const uint32_t Bb = smb + FL_KB + ((p == 1) ? 8192 : 0);
            mma_tile64(Ab, Bb, rA, cA, rB, cB, acc_o);
        }
    }

    // ---- epilogue: normalize, split, write ctx ----
    const int b = bh >> 4, h = bh & 15;
#pragma unroll
    for (int i = 0; i < 2; i++)
#pragma unroll
    for (int half = 0; half < 2; half++) {
        const int r = m0 + wm * 32 + i * 16 + g + half * 8;
        const float inv = 1.0f / srow[i][half];
        const size_t rowoff = ((size_t)(b * S_ + r)) * DM + h * DK;
#pragma unroll
        for (int j = 0; j < 4; j++)
#pragma unroll
        for (int q = 0; q < 2; q++) {
            const int d = wn * 32 + j * 8 + 2 * tq + q;
            __nv_bfloat16 hh, ll; split2(acc_o[i][j][half * 2 + q] * inv, hh, ll);
            g_ctxhi[rowoff + d] = hh;
            g_ctxlo[rowoff + d] = ll;
        }
    }
}

// ---------------------------------------------------------------------------
// out: out = ctx @ Wo^T + bo.  grid (16, 32)
// ---------------------------------------------------------------------------
__global__ __launch_bounds__(256) void out_kernel(float* __restrict__ out,
                                                  const float* __restrict__ bo)
{
    extern __shared__ char sm[];
    const int n0 = blockIdx.x * 64;
    const int m0 = blockIdx.y * 128;

    float acc[2][4][4];
#pragma unroll
    for (int i = 0; i < 2; i++)
#pragma unroll
        for (int j = 0; j < 4; j++)
#pragma unroll
            for (int q = 0; q < 4; q++) acc[i][j][q] = 0.f;

    mma_loop(g_ctxhi + (size_t)m0 * DM, g_ctxlo + (size_t)m0 * DM, DM,
             g_Wohi + (size_t)n0 * DM, g_Wolo + (size_t)n0 * DM, DM, DM, sm, acc);

    const int lane = threadIdx.x & 31, wid = threadIdx.x >> 5;
    const int wm = wid >> 1, wn = wid & 1;
#pragma unroll
    for (int i = 0; i < 2; i++)
#pragma unroll
    for (int half = 0; half < 2; half++) {
        const int r = m0 + wm * 32 + i * 16 + (lane >> 2) + half * 8;
#pragma unroll
        for (int j = 0; j < 4; j++) {
            const int c = n0 + wn * 32 + j * 8 + 2 * (lane & 3);
            float2 o = { acc[i][j][half * 2] + bo[c],
                         acc[i][j][half * 2 + 1] + bo[c + 1] };
            *(float2*)(out + (size_t)r * DM + c) = o;
        }
    }
}

// ---------------------------------------------------------------------------
// launcher — no __device__ symbol referenced from host code.
// ---------------------------------------------------------------------------
extern "C" void kernel_launch(void* const* d_in, const int* in_sizes, int n_in,
                              void* d_out, int out_size)
{
    (void)in_sizes; (void)n_in; (void)out_size;
    const float* Q  = (const float*)d_in[0];
    const float* K  = (const float*)d_in[1];
    const float* V  = (const float*)d_in[2];
    const float* bq = (const float*)d_in[4];
    const float* bk = (const float*)d_in[6];
    const float* bv = (const float*)d_in[8];
    const float* bo = (const float*)d_in[10];
    float* out = (float*)d_out;

    cudaFuncSetAttribute(proj_kernel,  cudaFuncAttributeMaxDynamicSharedMemorySize, GE_SZ);
    cudaFuncSetAttribute(out_kernel,   cudaFuncAttributeMaxDynamicSharedMemorySize, GE_SZ);
    cudaFuncSetAttribute(flash_kernel, cudaFuncAttributeMaxDynamicSharedMemorySize, FL_SZ);

    const int nX4 = MROWS * DM / 4;
    const int nW4 = DM * DM / 4;
    cvt_kernel<<<(nX4 + 255) / 256, 256>>>(Q,                     0, nX4);
    cvt_kernel<<<(nX4 + 255) / 256, 256>>>(K,                     1, nX4);
    cvt_kernel<<<(nX4 + 255) / 256, 256>>>(V,                     2, nX4);
    cvt_kernel<<<(nW4 + 255) / 256, 256>>>((const float*)d_in[3], 3, nW4);
    cvt_kernel<<<(nW4 + 255) / 256, 256>>>((const float*)d_in[5], 4, nW4);
    cvt_kernel<<<(nW4 + 255) / 256, 256>>>((const float*)d_in[7], 5, nW4);
    cvt_kernel<<<(nW4 + 255) / 256, 256>>>((const float*)d_in[9], 6, nW4);

    proj_kernel <<<dim3(DM / 64, MROWS / 128, 3), 256, GE_SZ>>>(bq, bk, bv);
    flash_kernel<<<dim3(S_ / 128, BH), 256, FL_SZ>>>();
    out_kernel  <<<dim3(DM / 64, MROWS / 128),    256, GE_SZ>>>(out, bo);
}

// round 9
// speedup vs baseline: 4.1524x; 1.4250x over previous
#include <cuda_runtime.h>
#include <cuda_bf16.h>
#include <cuda_fp16.h>
#include <cstdint>

// ===========================================================================
// MHA  B=2 S=2048 DM=1024 H=16 DK=64 — Round 9:
//   * flash: single-pass fp16 S (q,k fp16; abs score err ~2e-4), FA2
//     register-P (warp = 16 rows x 64 keys; P never hits smem), 3-pass bf16 PV
//   * proj/out: unchanged cp.async 2-stage split-bf16 HMMA pipelines
//   * cvt merged into one launch
// ===========================================================================

#define B_    2
#define S_    2048
#define H_    16
#define DK    64
#define DM    1024
#define MROWS (B_ * S_)   // 4096
#define BH    (B_ * H_)   // 32

// ---------------- device scratch ----------------
__device__ __nv_bfloat16 g_Qhi[MROWS * DM], g_Qlo[MROWS * DM];
__device__ __nv_bfloat16 g_Khi[MROWS * DM], g_Klo[MROWS * DM];
__device__ __nv_bfloat16 g_Vhi[MROWS * DM], g_Vlo[MROWS * DM];
__device__ __nv_bfloat16 g_Wqhi[DM * DM], g_Wqlo[DM * DM];
__device__ __nv_bfloat16 g_Wkhi[DM * DM], g_Wklo[DM * DM];
__device__ __nv_bfloat16 g_Wvhi[DM * DM], g_Wvlo[DM * DM];
__device__ __nv_bfloat16 g_Wohi[DM * DM], g_Wolo[DM * DM];
__device__ unsigned short g_q16[BH * S_ * DK];   // fp16, pre-scaled by 0.125
__device__ unsigned short g_k16[BH * S_ * DK];   // fp16
__device__ __nv_bfloat16 g_vThi[BH * DK * S_], g_vTlo[BH * DK * S_];
__device__ __nv_bfloat16 g_ctxhi[MROWS * DM], g_ctxlo[MROWS * DM];

// ---------------- helpers ----------------
__device__ __forceinline__ uint32_t smem_u32(const void* p) {
    uint32_t a;
    asm("{ .reg .u64 t; cvta.to.shared.u64 t, %1; cvt.u32.u64 %0, t; }" : "=r"(a) : "l"(p));
    return a;
}
#define SWZ(b) ((b) ^ (((b) >> 3) & 0x70))

__device__ __forceinline__ void ldsm4(uint32_t r[4], uint32_t addr) {
    asm volatile("ldmatrix.sync.aligned.m8n8.x4.shared.b16 {%0,%1,%2,%3}, [%4];"
        : "=r"(r[0]), "=r"(r[1]), "=r"(r[2]), "=r"(r[3]) : "r"(addr));
}
__device__ __forceinline__ void cpa16(uint32_t dst, const void* src) {
    asm volatile("cp.async.cg.shared.global [%0], [%1], 16;" :: "r"(dst), "l"(src) : "memory");
}
#define CP_COMMIT() asm volatile("cp.async.commit_group;" ::: "memory")
#define CP_WAIT0()  asm volatile("cp.async.wait_group 0;" ::: "memory")

__device__ __forceinline__ void hmma_bf16(float c[4], const uint32_t a[4], const uint32_t b[2]) {
    asm volatile("mma.sync.aligned.m16n8k16.row.col.f32.bf16.bf16.f32 "
        "{%0,%1,%2,%3}, {%4,%5,%6,%7}, {%8,%9}, {%0,%1,%2,%3};"
        : "+f"(c[0]), "+f"(c[1]), "+f"(c[2]), "+f"(c[3])
        : "r"(a[0]), "r"(a[1]), "r"(a[2]), "r"(a[3]), "r"(b[0]), "r"(b[1]));
}
__device__ __forceinline__ void hmma_f16(float c[4], const uint32_t a[4], const uint32_t b[2]) {
    asm volatile("mma.sync.aligned.m16n8k16.row.col.f32.f16.f16.f32 "
        "{%0,%1,%2,%3}, {%4,%5,%6,%7}, {%8,%9}, {%0,%1,%2,%3};"
        : "+f"(c[0]), "+f"(c[1]), "+f"(c[2]), "+f"(c[3])
        : "r"(a[0]), "r"(a[1]), "r"(a[2]), "r"(a[3]), "r"(b[0]), "r"(b[1]));
}
__device__ __forceinline__ uint32_t pk2(__nv_bfloat16 a, __nv_bfloat16 b) {
    return (uint32_t)__bfloat16_as_ushort(a) | ((uint32_t)__bfloat16_as_ushort(b) << 16);
}
__device__ __forceinline__ uint32_t pkh2(float a, float b) {
    __half2 h2 = __floats2half2_rn(a, b);
    return *(uint32_t*)&h2;
}
__device__ __forceinline__ void split2(float x, __nv_bfloat16& h, __nv_bfloat16& l) {
    h = __float2bfloat16(x);
    l = __float2bfloat16(x - __bfloat162float(h));
}

// ---------------- proj/out pipelined smem: 2 stages x 48 KB ----------------
#define STG_AHI 0
#define STG_ALO 16384
#define STG_BHI 32768
#define STG_BLO 40960
#define STG_SZ  49152
#define GE_SZ   (2 * STG_SZ)

// ---------------------------------------------------------------------------
// one 64-deep k-tile of split MMAs for the 4x2-warp GEMM kernels
// ---------------------------------------------------------------------------
__device__ __forceinline__ void mma_tile64(
    uint32_t Ab, uint32_t Bb, int rA, int cA, int rB, int cB, float acc[2][4][4])
{
#pragma unroll
    for (int ks = 0; ks < 4; ks++) {
        uint32_t a[2][4], b0[4], b1[4];
        ldsm4(a[0], Ab + SWZ((uint32_t)((rA)      * 128 + cA + ks * 32)));
        ldsm4(a[1], Ab + SWZ((uint32_t)((rA + 16) * 128 + cA + ks * 32)));
        ldsm4(b0,   Bb + SWZ((uint32_t)((rB)      * 128 + cB + ks * 32)));
        ldsm4(b1,   Bb + SWZ((uint32_t)((rB + 16) * 128 + cB + ks * 32)));
        uint32_t bb[4][2] = { {b0[0],b0[1]}, {b0[2],b0[3]},
                              {b1[0],b1[1]}, {b1[2],b1[3]} };
#pragma unroll
        for (int i = 0; i < 2; i++)
#pragma unroll
            for (int j = 0; j < 4; j++)
                hmma_bf16(acc[i][j], a[i], bb[j]);
    }
}

// ---------------------------------------------------------------------------
// GEMM mainloop (proj/out): 2-stage cp.async pipeline, 3-pass split MMA.
// ---------------------------------------------------------------------------
__device__ __forceinline__ void mma_loop(
    const __nv_bfloat16* __restrict__ Ah, const __nv_bfloat16* __restrict__ Al, int lda,
    const __nv_bfloat16* __restrict__ Bh, const __nv_bfloat16* __restrict__ Bl, int ldb,
    int K, char* sm, float acc[2][4][4])
{
    const int tid  = threadIdx.x;
    const int lane = tid & 31;
    const int wid  = tid >> 5;
    const int wm   = wid >> 1;
    const int wn   = wid & 1;
    const uint32_t smb = smem_u32(sm);

    const int rA = wm * 32 + (lane & 15);
    const int cA = (lane >> 4) << 4;
    const int rB = wn * 32 + (lane & 7) + ((lane & 16) >> 1);
    const int cB = (lane & 8) << 1;

    auto issue = [&](int ch, uint32_t st) {
        const int k0 = ch << 6;
#pragma unroll
        for (int i = 0; i < 4; i++) {
            int e = (tid + (i << 8)) << 3;
            int row = e >> 6, col = e & 63;
            uint32_t sw = SWZ((uint32_t)(row * 128 + col * 2));
            cpa16(st + STG_AHI + sw, Ah + (size_t)row * lda + k0 + col);
            cpa16(st + STG_ALO + sw, Al + (size_t)row * lda + k0 + col);
        }
#pragma unroll
        for (int i = 0; i < 2; i++) {
            int e = (tid + (i << 8)) << 3;
            int row = e >> 6, col = e & 63;
            uint32_t sw = SWZ((uint32_t)(row * 128 + col * 2));
            cpa16(st + STG_BHI + sw, Bh + (size_t)row * ldb + k0 + col);
            cpa16(st + STG_BLO + sw, Bl + (size_t)row * ldb + k0 + col);
        }
    };

    const int nch = K >> 6;
    issue(0, smb); CP_COMMIT();
    for (int ch = 0; ch < nch; ch++) {
        CP_WAIT0();
        __syncthreads();
        if (ch + 1 < nch) { issue(ch + 1, smb + ((ch + 1) & 1) * STG_SZ); CP_COMMIT(); }
        const uint32_t st = smb + (ch & 1) * STG_SZ;
#pragma unroll
        for (int p = 0; p < 3; p++) {
            const uint32_t Ab = st + ((p == 2) ? STG_ALO : STG_AHI);
            const uint32_t Bb = st + ((p == 1) ? STG_BLO : STG_BHI);
            mma_tile64(Ab, Bb, rA, cA, rB, cB, acc);
        }
    }
}

// ---------------------------------------------------------------------------
// cvt (merged): fp32 -> (hi, lo) bf16 for X's and W's, one launch.
// ---------------------------------------------------------------------------
#define NX4 (MROWS * DM / 4)   // 1M quads per X tensor
#define NW4 (DM * DM / 4)      // 256K quads per W tensor
__global__ void cvt_kernel(const float* __restrict__ Q, const float* __restrict__ K,
                           const float* __restrict__ V, const float* __restrict__ Wq,
                           const float* __restrict__ Wk, const float* __restrict__ Wv,
                           const float* __restrict__ Wo)
{
    int i = blockIdx.x * blockDim.x + threadIdx.x;
    const float* src; __nv_bfloat16 *hi, *lo; int off;
    if (i < NX4)            { src = Q;  hi = g_Qhi;  lo = g_Qlo;  off = i; }
    else if (i < 2 * NX4)   { src = K;  hi = g_Khi;  lo = g_Klo;  off = i - NX4; }
    else if (i < 3 * NX4)   { src = V;  hi = g_Vhi;  lo = g_Vlo;  off = i - 2 * NX4; }
    else {
        int w = i - 3 * NX4;
        int t = w / NW4; off = w - t * NW4;
        if (t == 0)      { src = Wq; hi = g_Wqhi; lo = g_Wqlo; }
        else if (t == 1) { src = Wk; hi = g_Wkhi; lo = g_Wklo; }
        else if (t == 2) { src = Wv; hi = g_Wvhi; lo = g_Wvlo; }
        else             { src = Wo; hi = g_Wohi; lo = g_Wolo; }
    }
    float4 v = ((const float4*)src)[off];
    __nv_bfloat16 h[4], l[4];
    split2(v.x, h[0], l[0]); split2(v.y, h[1], l[1]);
    split2(v.z, h[2], l[2]); split2(v.w, h[3], l[3]);
    ((uint2*)hi)[off] = make_uint2(pk2(h[0], h[1]), pk2(h[2], h[3]));
    ((uint2*)lo)[off] = make_uint2(pk2(l[0], l[1]), pk2(l[2], l[3]));
}

// ---------------------------------------------------------------------------
// proj: z=0 -> q (fp16, x0.125), z=1 -> k (fp16), z=2 -> vT (bf16 hi/lo).
// grid (16, 32, 3)
// ---------------------------------------------------------------------------
__global__ __launch_bounds__(256) void proj_kernel(
    const float* __restrict__ bq, const float* __restrict__ bk,
    const float* __restrict__ bv)
{
    extern __shared__ char sm[];
    const int z  = blockIdx.z;
    const int n0 = blockIdx.x * 64;
    const int m0 = blockIdx.y * 128;

    const __nv_bfloat16 *Ah, *Al, *Bh, *Bl;
    const float* bias;
    if (z == 0)      { Ah = g_Qhi; Al = g_Qlo; Bh = g_Wqhi; Bl = g_Wqlo; bias = bq; }
    else if (z == 1) { Ah = g_Khi; Al = g_Klo; Bh = g_Wkhi; Bl = g_Wklo; bias = bk; }
    else             { Ah = g_Vhi; Al = g_Vlo; Bh = g_Wvhi; Bl = g_Wvlo; bias = bv; }

    float acc[2][4][4];
#pragma unroll
    for (int i = 0; i < 2; i++)
#pragma unroll
        for (int j = 0; j < 4; j++)
#pragma unroll
            for (int q = 0; q < 4; q++) acc[i][j][q] = 0.f;

    mma_loop(Ah + (size_t)m0 * DM, Al + (size_t)m0 * DM, DM,
             Bh + (size_t)n0 * DM, Bl + (size_t)n0 * DM, DM, DM, sm, acc);

    const int lane = threadIdx.x & 31, wid = threadIdx.x >> 5;
    const int wm = wid >> 1, wn = wid & 1;
#pragma unroll
    for (int i = 0; i < 2; i++)
#pragma unroll
    for (int half = 0; half < 2; half++) {
        const int r = m0 + wm * 32 + i * 16 + (lane >> 2) + half * 8;
        const int b = r >> 11, s = r & (S_ - 1);
#pragma unroll
        for (int j = 0; j < 4; j++) {
            const int n = n0 + wn * 32 + j * 8 + 2 * (lane & 3);
            float v0 = acc[i][j][half * 2]     + bias[n];
            float v1 = acc[i][j][half * 2 + 1] + bias[n + 1];
            const int hh = n >> 6, dk = n & 63;
            const size_t bh = (size_t)(b * H_ + hh);
            if (z == 0) {
                *(uint32_t*)&g_q16[(bh * S_ + s) * DK + dk] = pkh2(v0 * 0.125f, v1 * 0.125f);
            } else if (z == 1) {
                *(uint32_t*)&g_k16[(bh * S_ + s) * DK + dk] = pkh2(v0, v1);
            } else {
                __nv_bfloat16 h0, l0, h1, l1;
                split2(v0, h0, l0); split2(v1, h1, l1);
                g_vThi[(bh * DK + dk)     * S_ + s] = h0;
                g_vTlo[(bh * DK + dk)     * S_ + s] = l0;
                g_vThi[(bh * DK + dk + 1) * S_ + s] = h1;
                g_vTlo[(bh * DK + dk + 1) * S_ + s] = l1;
            }
        }
    }
}

// ---------------- flash smem layout (dynamic, 40 KB) ----------------
#define FQ  0          // 16 KB fp16 q tile (128 x 64)
#define FK  16384      // 8 KB  fp16 K chunk (64 x 64)
#define FVH 24576      // 8 KB  bf16 vT hi (64 dk x 64 keys)
#define FVL 32768      // 8 KB  bf16 vT lo
#define FL_SZ 40960

// ---------------------------------------------------------------------------
// flash: fused scores+softmax+pv. FA2 layout: warp = 16 rows x 64 keys,
// P stays in registers. grid (16, BH), 256 threads (8 warps).
// ---------------------------------------------------------------------------
__global__ __launch_bounds__(256, 2) void flash_kernel()
{
    extern __shared__ char sm[];
    const uint32_t smb = smem_u32(sm);

    const int bh = blockIdx.y;
    const int m0 = blockIdx.x * 128;
    const size_t qoff = (size_t)bh * S_ * DK;
    const size_t voff = (size_t)bh * DK * S_;

    const int tid  = threadIdx.x;
    const int lane = tid & 31;
    const int wid  = tid >> 5;
    const int g    = lane >> 2;
    const int tq   = lane & 3;

    const int rA  = wid * 16 + (lane & 15);
    const int cA  = (lane >> 4) << 4;
    const int rB0 = (lane & 7) + ((lane & 16) >> 1);
    const int cB  = (lane & 8) << 1;

    auto issueK = [&](int n0) {
#pragma unroll
        for (int i = 0; i < 2; i++) {
            int e = (tid + (i << 8)) << 3;
            int row = e >> 6, col = e & 63;
            uint32_t sw = SWZ((uint32_t)(row * 128 + col * 2));
            cpa16(smb + FK + sw, g_k16 + qoff + (size_t)(n0 + row) * DK + col);
        }
    };
    auto issueV = [&](int n0) {
#pragma unroll
        for (int i = 0; i < 2; i++) {
            int e = (tid + (i << 8)) << 3;
            int row = e >> 6, col = e & 63;     // row = dk, col = key
            uint32_t sw = SWZ((uint32_t)(row * 128 + col * 2));
            cpa16(smb + FVH + sw, g_vThi + voff + (size_t)row * S_ + n0 + col);
            cpa16(smb + FVL + sw, g_vTlo + voff + (size_t)row * S_ + n0 + col);
        }
    };

    // ---- issue Q (persistent) + K chunk 0 ----
#pragma unroll
    for (int i = 0; i < 4; i++) {
        int e = (tid + (i << 8)) << 3;
        int row = e >> 6, col = e & 63;
        uint32_t sw = SWZ((uint32_t)(row * 128 + col * 2));
        cpa16(smb + FQ + sw, g_q16 + qoff + (size_t)(m0 + row) * DK + col);
    }
    issueK(0);
    CP_COMMIT();

    float acc_o[8][4];
#pragma unroll
    for (int j = 0; j < 8; j++)
#pragma unroll
        for (int q = 0; q < 4; q++) acc_o[j][q] = 0.f;
    float m0r = -1e30f, m1r = -1e30f, s0r = 0.f, s1r = 0.f;

    for (int ch = 0; ch < S_ / 64; ch++) {
        const int n0 = ch << 6;

        CP_WAIT0();
        __syncthreads();                 // K(ch)+Q visible; all warps done with V(ch-1)
        issueV(n0); CP_COMMIT();         // V(ch) flies during S + softmax

        // ---- S = q k^T, single-pass fp16 (q pre-scaled) ----
        float s[8][4];
#pragma unroll
        for (int j = 0; j < 8; j++)
#pragma unroll
            for (int q = 0; q < 4; q++) s[j][q] = 0.f;
#pragma unroll
        for (int ks = 0; ks < 4; ks++) {
            uint32_t a[4];
            ldsm4(a, smb + FQ + SWZ((uint32_t)(rA * 128 + cA + ks * 32)));
            uint32_t b[4][4];
#pragma unroll
            for (int nb = 0; nb < 4; nb++)
                ldsm4(b[nb], smb + FK + SWZ((uint32_t)((rB0 + 16 * nb) * 128 + cB + ks * 32)));
#pragma unroll
            for (int j = 0; j < 8; j++) {
                uint32_t bb[2] = { b[j >> 1][(j & 1) * 2], b[j >> 1][(j & 1) * 2 + 1] };
                hmma_f16(s[j], a, bb);
            }
        }

        // ---- online softmax, fully in registers (rows g and g+8) ----
        float mx0 = -1e30f, mx1 = -1e30f;
#pragma unroll
        for (int j = 0; j < 8; j++) {
            mx0 = fmaxf(mx0, fmaxf(s[j][0], s[j][1]));
            mx1 = fmaxf(mx1, fmaxf(s[j][2], s[j][3]));
        }
        mx0 = fmaxf(mx0, __shfl_xor_sync(~0u, mx0, 1));
        mx0 = fmaxf(mx0, __shfl_xor_sync(~0u, mx0, 2));
        mx1 = fmaxf(mx1, __shfl_xor_sync(~0u, mx1, 1));
        mx1 = fmaxf(mx1, __shfl_xor_sync(~0u, mx1, 2));

        const float mn0 = fmaxf(m0r, mx0), mn1 = fmaxf(m1r, mx1);
        const float al0 = __expf(m0r - mn0), al1 = __expf(m1r - mn1);
        m0r = mn0; m1r = mn1;

        float ps0 = 0.f, ps1 = 0.f;
#pragma unroll
        for (int j = 0; j < 8; j++) {
            s[j][0] = __expf(s[j][0] - mn0);
            s[j][1] = __expf(s[j][1] - mn0);
            s[j][2] = __expf(s[j][2] - mn1);
            s[j][3] = __expf(s[j][3] - mn1);
            ps0 += s[j][0] + s[j][1];
            ps1 += s[j][2] + s[j][3];
            acc_o[j][0] *= al0; acc_o[j][1] *= al0;
            acc_o[j][2] *= al1; acc_o[j][3] *= al1;
        }
        ps0 += __shfl_xor_sync(~0u, ps0, 1);
        ps0 += __shfl_xor_sync(~0u, ps0, 2);
        ps1 += __shfl_xor_sync(~0u, ps1, 1);
        ps1 += __shfl_xor_sync(~0u, ps1, 2);
        s0r = s0r * al0 + ps0;
        s1r = s1r * al1 + ps1;

        CP_WAIT0();
        __syncthreads();                 // V(ch) visible; all warps done with K(ch)
        if (ch + 1 < S_ / 64) { issueK(n0 + 64); CP_COMMIT(); }  // K(ch+1) flies during PV

        // ---- O += P @ V, 3-pass split bf16, P fragments from registers ----
#pragma unroll
        for (int ks = 0; ks < 4; ks++) {
            uint32_t ah[4], al[4];
            {
                __nv_bfloat16 h0, l0, h1, l1;
                split2(s[2 * ks][0], h0, l0); split2(s[2 * ks][1], h1, l1);
                ah[0] = pk2(h0, h1); al[0] = pk2(l0, l1);
                split2(s[2 * ks][2], h0, l0); split2(s[2 * ks][3], h1, l1);
                ah[1] = pk2(h0, h1); al[1] = pk2(l0, l1);
                split2(s[2 * ks + 1][0], h0, l0); split2(s[2 * ks + 1][1], h1, l1);
                ah[2] = pk2(h0, h1); al[2] = pk2(l0, l1);
                split2(s[2 * ks + 1][2], h0, l0); split2(s[2 * ks + 1][3], h1, l1);
                ah[3] = pk2(h0, h1); al[3] = pk2(l0, l1);
            }
            uint32_t vh[4][4], vl[4][4];
#pragma unroll
            for (int nb = 0; nb < 4; nb++) {
                ldsm4(vh[nb], smb + FVH + SWZ((uint32_t)((rB0 + 16 * nb) * 128 + cB + ks * 32)));
                ldsm4(vl[nb], smb + FVL + SWZ((uint32_t)((rB0 + 16 * nb) * 128 + cB + ks * 32)));
            }
#pragma unroll
            for (int j = 0; j < 8; j++) {
                uint32_t bh2[2] = { vh[j >> 1][(j & 1) * 2], vh[j >> 1][(j & 1) * 2 + 1] };
                uint32_t bl2[2] = { vl[j >> 1][(j & 1) * 2], vl[j >> 1][(j & 1) * 2 + 1] };
                hmma_bf16(acc_o[j], ah, bh2);
                hmma_bf16(acc_o[j], ah, bl2);
                hmma_bf16(acc_o[j], al, bh2);
            }
        }
    }

    // ---- epilogue: normalize, split, write ctx ----
    const int b = bh >> 4, h = bh & 15;
    const float inv0 = 1.0f / s0r, inv1 = 1.0f / s1r;
    const int r0 = m0 + wid * 16 + g;
    const size_t ro0 = ((size_t)(b * S_ + r0)) * DM + h * DK;
    const size_t ro1 = ro0 + (size_t)8 * DM;
#pragma unroll
    for (int j = 0; j < 8; j++) {
        const int d = 8 * j + 2 * tq;
        __nv_bfloat16 h0, l0, h1, l1;
        split2(acc_o[j][0] * inv0, h0, l0); split2(acc_o[j][1] * inv0, h1, l1);
        *(uint32_t*)&g_ctxhi[ro0 + d] = pk2(h0, h1);
        *(uint32_t*)&g_ctxlo[ro0 + d] = pk2(l0, l1);
        split2(acc_o[j][2] * inv1, h0, l0); split2(acc_o[j][3] * inv1, h1, l1);
        *(uint32_t*)&g_ctxhi[ro1 + d] = pk2(h0, h1);
        *(uint32_t*)&g_ctxlo[ro1 + d] = pk2(l0, l1);
    }
}

// ---------------------------------------------------------------------------
// out: out = ctx @ Wo^T + bo.  grid (16, 32)
// ---------------------------------------------------------------------------
__global__ __launch_bounds__(256) void out_kernel(float* __restrict__ out,
                                                  const float* __restrict__ bo)
{
    extern __shared__ char sm[];
    const int n0 = blockIdx.x * 64;
    const int m0 = blockIdx.y * 128;

    float acc[2][4][4];
#pragma unroll
    for (int i = 0; i < 2; i++)
#pragma unroll
        for (int j = 0; j < 4; j++)
#pragma unroll
            for (int q = 0; q < 4; q++) acc[i][j][q] = 0.f;

    mma_loop(g_ctxhi + (size_t)m0 * DM, g_ctxlo + (size_t)m0 * DM, DM,
             g_Wohi + (size_t)n0 * DM, g_Wolo + (size_t)n0 * DM, DM, DM, sm, acc);

    const int lane = threadIdx.x & 31, wid = threadIdx.x >> 5;
    const int wm = wid >> 1, wn = wid & 1;
#pragma unroll
    for (int i = 0; i < 2; i++)
#pragma unroll
    for (int half = 0; half < 2; half++) {
        const int r = m0 + wm * 32 + i * 16 + (lane >> 2) + half * 8;
#pragma unroll
        for (int j = 0; j < 4; j++) {
            const int c = n0 + wn * 32 + j * 8 + 2 * (lane & 3);
            float2 o = { acc[i][j][half * 2] + bo[c],
                         acc[i][j][half * 2 + 1] + bo[c + 1] };
            *(float2*)(out + (size_t)r * DM + c) = o;
        }
    }
}

// ---------------------------------------------------------------------------
// launcher — no __device__ symbol referenced from host code.
// ---------------------------------------------------------------------------
extern "C" void kernel_launch(void* const* d_in, const int* in_sizes, int n_in,
                              void* d_out, int out_size)
{
    (void)in_sizes; (void)n_in; (void)out_size;
    const float* Q  = (const float*)d_in[0];
    const float* K  = (const float*)d_in[1];
    const float* V  = (const float*)d_in[2];
    const float* bq = (const float*)d_in[4];
    const float* bk = (const float*)d_in[6];
    const float* bv = (const float*)d_in[8];
    const float* bo = (const float*)d_in[10];
    float* out = (float*)d_out;

    cudaFuncSetAttribute(proj_kernel,  cudaFuncAttributeMaxDynamicSharedMemorySize, GE_SZ);
    cudaFuncSetAttribute(out_kernel,   cudaFuncAttributeMaxDynamicSharedMemorySize, GE_SZ);
    cudaFuncSetAttribute(flash_kernel, cudaFuncAttributeMaxDynamicSharedMemorySize, FL_SZ);

    const int total4 = 3 * NX4 + 4 * NW4;
    cvt_kernel<<<total4 / 256, 256>>>(Q, K, V,
                                      (const float*)d_in[3], (const float*)d_in[5],
                                      (const float*)d_in[7], (const float*)d_in[9]);

    proj_kernel <<<dim3(DM / 64, MROWS / 128, 3), 256, GE_SZ>>>(bq, bk, bv);
    flash_kernel<<<dim3(S_ / 128, BH), 256, FL_SZ>>>();
    out_kernel  <<<dim3(DM / 64, MROWS / 128),    256, GE_SZ>>>(out, bo);
}

// round 10
// speedup vs baseline: 6.6423x; 1.5996x over previous
#include <cuda_runtime.h>
#include <cuda_bf16.h>
#include <cuda_fp16.h>
#include <cstdint>

// ===========================================================================
// MHA  B=2 S=2048 DM=1024 H=16 DK=64 — Round 10: all-fp16 tensor path
//   proj/out: 2-pass fp16 (A split hi/lo, B single fp16)
//   flash   : single-pass fp16 S  +  single-pass fp16 PV (register P)
//   cp.async pipelines throughout; ldmatrix fragments.
// ===========================================================================

#define B_    2
#define S_    2048
#define H_    16
#define DK    64
#define DM    1024
#define MROWS (B_ * S_)   // 4096
#define BH    (B_ * H_)   // 32

typedef unsigned short u16;

// ---------------- device scratch ----------------
__device__ u16 g_Qh16[MROWS * DM], g_Ql16[MROWS * DM];
__device__ u16 g_Kh16[MROWS * DM], g_Kl16[MROWS * DM];
__device__ u16 g_Vh16[MROWS * DM], g_Vl16[MROWS * DM];
__device__ u16 g_Wq16[DM * DM], g_Wk16[DM * DM], g_Wv16[DM * DM], g_Wo16[DM * DM];
__device__ u16 g_q16[BH * S_ * DK];            // fp16, pre-scaled by 0.125
__device__ u16 g_k16[BH * S_ * DK];
__device__ u16 g_vT16[BH * DK * S_];           // transposed V, single fp16
__device__ u16 g_ctxh16[MROWS * DM], g_ctxl16[MROWS * DM];

// ---------------- helpers ----------------
__device__ __forceinline__ uint32_t smem_u32(const void* p) {
    uint32_t a;
    asm("{ .reg .u64 t; cvta.to.shared.u64 t, %1; cvt.u32.u64 %0, t; }" : "=r"(a) : "l"(p));
    return a;
}
#define SWZ(b) ((b) ^ (((b) >> 3) & 0x70))

__device__ __forceinline__ void ldsm4(uint32_t r[4], uint32_t addr) {
    asm volatile("ldmatrix.sync.aligned.m8n8.x4.shared.b16 {%0,%1,%2,%3}, [%4];"
        : "=r"(r[0]), "=r"(r[1]), "=r"(r[2]), "=r"(r[3]) : "r"(addr));
}
__device__ __forceinline__ void cpa16(uint32_t dst, const void* src) {
    asm volatile("cp.async.cg.shared.global [%0], [%1], 16;" :: "r"(dst), "l"(src) : "memory");
}
#define CP_COMMIT() asm volatile("cp.async.commit_group;" ::: "memory")
#define CP_WAIT0()  asm volatile("cp.async.wait_group 0;" ::: "memory")

__device__ __forceinline__ void hmma_f16(float c[4], const uint32_t a[4], const uint32_t b[2]) {
    asm volatile("mma.sync.aligned.m16n8k16.row.col.f32.f16.f16.f32 "
        "{%0,%1,%2,%3}, {%4,%5,%6,%7}, {%8,%9}, {%0,%1,%2,%3};"
        : "+f"(c[0]), "+f"(c[1]), "+f"(c[2]), "+f"(c[3])
        : "r"(a[0]), "r"(a[1]), "r"(a[2]), "r"(a[3]), "r"(b[0]), "r"(b[1]));
}
__device__ __forceinline__ uint32_t pkh2(float a, float b) {
    __half2 h2 = __floats2half2_rn(a, b);
    return *(uint32_t*)&h2;
}
__device__ __forceinline__ void split2h(float x, __half& h, __half& l) {
    h = __float2half_rn(x);
    l = __float2half_rn(x - __half2float(h));
}
__device__ __forceinline__ uint32_t pkraw(__half a, __half b) {
    return (uint32_t)*(u16*)&a | ((uint32_t)*(u16*)&b << 16);
}

// ---------------- proj/out pipelined smem: 2 stages x 40 KB ----------------
#define STG_AH 0
#define STG_AL 16384
#define STG_B  32768
#define STG_SZ 40960
#define GE_SZ  (2 * STG_SZ)   // 80 KB dynamic

// ---------------------------------------------------------------------------
// one 64-deep k-tile of fp16 MMAs for the 4x2-warp GEMM kernels
// ---------------------------------------------------------------------------
__device__ __forceinline__ void mma_tile64(
    uint32_t Ab, uint32_t Bb, int rA, int cA, int rB, int cB, float acc[2][4][4])
{
#pragma unroll
    for (int ks = 0; ks < 4; ks++) {
        uint32_t a[2][4], b0[4], b1[4];
        ldsm4(a[0], Ab + SWZ((uint32_t)((rA)      * 128 + cA + ks * 32)));
        ldsm4(a[1], Ab + SWZ((uint32_t)((rA + 16) * 128 + cA + ks * 32)));
        ldsm4(b0,   Bb + SWZ((uint32_t)((rB)      * 128 + cB + ks * 32)));
        ldsm4(b1,   Bb + SWZ((uint32_t)((rB + 16) * 128 + cB + ks * 32)));
        uint32_t bb[4][2] = { {b0[0],b0[1]}, {b0[2],b0[3]},
                              {b1[0],b1[1]}, {b1[2],b1[3]} };
#pragma unroll
        for (int i = 0; i < 2; i++)
#pragma unroll
            for (int j = 0; j < 4; j++)
                hmma_f16(acc[i][j], a[i], bb[j]);
    }
}

// ---------------------------------------------------------------------------
// GEMM mainloop (proj/out): 2-stage cp.async pipeline, 2-pass fp16 split-A.
// ---------------------------------------------------------------------------
__device__ __forceinline__ void mma_loop(
    const u16* __restrict__ Ah, const u16* __restrict__ Al, int lda,
    const u16* __restrict__ Bp, int ldb,
    int K, char* sm, float acc[2][4][4])
{
    const int tid  = threadIdx.x;
    const int lane = tid & 31;
    const int wid  = tid >> 5;
    const int wm   = wid >> 1;
    const int wn   = wid & 1;
    const uint32_t smb = smem_u32(sm);

    const int rA = wm * 32 + (lane & 15);
    const int cA = (lane >> 4) << 4;
    const int rB = wn * 32 + (lane & 7) + ((lane & 16) >> 1);
    const int cB = (lane & 8) << 1;

    auto issue = [&](int ch, uint32_t st) {
        const int k0 = ch << 6;
#pragma unroll
        for (int i = 0; i < 4; i++) {
            int e = (tid + (i << 8)) << 3;
            int row = e >> 6, col = e & 63;
            uint32_t sw = SWZ((uint32_t)(row * 128 + col * 2));
            cpa16(st + STG_AH + sw, Ah + (size_t)row * lda + k0 + col);
            cpa16(st + STG_AL + sw, Al + (size_t)row * lda + k0 + col);
        }
#pragma unroll
        for (int i = 0; i < 2; i++) {
            int e = (tid + (i << 8)) << 3;
            int row = e >> 6, col = e & 63;
            uint32_t sw = SWZ((uint32_t)(row * 128 + col * 2));
            cpa16(st + STG_B + sw, Bp + (size_t)row * ldb + k0 + col);
        }
    };

    const int nch = K >> 6;
    issue(0, smb); CP_COMMIT();
    for (int ch = 0; ch < nch; ch++) {
        CP_WAIT0();
        __syncthreads();
        if (ch + 1 < nch) { issue(ch + 1, smb + ((ch + 1) & 1) * STG_SZ); CP_COMMIT(); }
        const uint32_t st = smb + (ch & 1) * STG_SZ;
        mma_tile64(st + STG_AH, st + STG_B, rA, cA, rB, cB, acc);
        mma_tile64(st + STG_AL, st + STG_B, rA, cA, rB, cB, acc);
    }
}

// ---------------------------------------------------------------------------
// cvt (merged): X -> fp16 (hi, lo); W -> fp16 single. One launch.
// ---------------------------------------------------------------------------
#define NX4 (MROWS * DM / 4)   // 1M quads per X tensor
#define NW4 (DM * DM / 4)      // 256K quads per W tensor
__global__ void cvt_kernel(const float* __restrict__ Q, const float* __restrict__ K,
                           const float* __restrict__ V, const float* __restrict__ Wq,
                           const float* __restrict__ Wk, const float* __restrict__ Wv,
                           const float* __restrict__ Wo)
{
    int i = blockIdx.x * blockDim.x + threadIdx.x;
    if (i < 3 * NX4) {
        const float* src; u16 *hi, *lo; int off;
        if (i < NX4)          { src = Q; hi = g_Qh16; lo = g_Ql16; off = i; }
        else if (i < 2 * NX4) { src = K; hi = g_Kh16; lo = g_Kl16; off = i - NX4; }
        else                  { src = V; hi = g_Vh16; lo = g_Vl16; off = i - 2 * NX4; }
        float4 v = ((const float4*)src)[off];
        __half h[4], l[4];
        split2h(v.x, h[0], l[0]); split2h(v.y, h[1], l[1]);
        split2h(v.z, h[2], l[2]); split2h(v.w, h[3], l[3]);
        ((uint2*)hi)[off] = make_uint2(pkraw(h[0], h[1]), pkraw(h[2], h[3]));
        ((uint2*)lo)[off] = make_uint2(pkraw(l[0], l[1]), pkraw(l[2], l[3]));
    } else {
        int w = i - 3 * NX4;
        int t = w / NW4, off = w - t * NW4;
        const float* src; u16* dst;
        if (t == 0)      { src = Wq; dst = g_Wq16; }
        else if (t == 1) { src = Wk; dst = g_Wk16; }
        else if (t == 2) { src = Wv; dst = g_Wv16; }
        else             { src = Wo; dst = g_Wo16; }
        float4 v = ((const float4*)src)[off];
        ((uint2*)dst)[off] = make_uint2(pkh2(v.x, v.y), pkh2(v.z, v.w));
    }
}

// ---------------------------------------------------------------------------
// proj: z=0 -> q (fp16, x0.125), z=1 -> k (fp16), z=2 -> vT (fp16).
// grid (16, 32, 3)
// ---------------------------------------------------------------------------
__global__ __launch_bounds__(256) void proj_kernel(
    const float* __restrict__ bq, const float* __restrict__ bk,
    const float* __restrict__ bv)
{
    extern __shared__ char sm[];
    const int z  = blockIdx.z;
    const int n0 = blockIdx.x * 64;
    const int m0 = blockIdx.y * 128;

    const u16 *Ah, *Al, *Bp;
    const float* bias;
    if (z == 0)      { Ah = g_Qh16; Al = g_Ql16; Bp = g_Wq16; bias = bq; }
    else if (z == 1) { Ah = g_Kh16; Al = g_Kl16; Bp = g_Wk16; bias = bk; }
    else             { Ah = g_Vh16; Al = g_Vl16; Bp = g_Wv16; bias = bv; }

    float acc[2][4][4];
#pragma unroll
    for (int i = 0; i < 2; i++)
#pragma unroll
        for (int j = 0; j < 4; j++)
#pragma unroll
            for (int q = 0; q < 4; q++) acc[i][j][q] = 0.f;

    mma_loop(Ah + (size_t)m0 * DM, Al + (size_t)m0 * DM, DM,
             Bp + (size_t)n0 * DM, DM, DM, sm, acc);

    const int lane = threadIdx.x & 31, wid = threadIdx.x >> 5;
    const int wm = wid >> 1, wn = wid & 1;
#pragma unroll
    for (int i = 0; i < 2; i++)
#pragma unroll
    for (int half = 0; half < 2; half++) {
        const int r = m0 + wm * 32 + i * 16 + (lane >> 2) + half * 8;
        const int b = r >> 11, s = r & (S_ - 1);
#pragma unroll
        for (int j = 0; j < 4; j++) {
            const int n = n0 + wn * 32 + j * 8 + 2 * (lane & 3);
            float v0 = acc[i][j][half * 2]     + bias[n];
            float v1 = acc[i][j][half * 2 + 1] + bias[n + 1];
            const int hh = n >> 6, dk = n & 63;
            const size_t bh = (size_t)(b * H_ + hh);
            if (z == 0) {
                *(uint32_t*)&g_q16[(bh * S_ + s) * DK + dk] = pkh2(v0 * 0.125f, v1 * 0.125f);
            } else if (z == 1) {
                *(uint32_t*)&g_k16[(bh * S_ + s) * DK + dk] = pkh2(v0, v1);
            } else {
                __half h0 = __float2half_rn(v0), h1 = __float2half_rn(v1);
                g_vT16[(bh * DK + dk)     * S_ + s] = *(u16*)&h0;
                g_vT16[(bh * DK + dk + 1) * S_ + s] = *(u16*)&h1;
            }
        }
    }
}

// ---------------- flash smem layout (dynamic, 32 KB) ----------------
#define FQ  0          // 16 KB fp16 q tile (128 x 64)
#define FK  16384      // 8 KB  fp16 K chunk (64 x 64)
#define FV  24576      // 8 KB  fp16 vT chunk (64 dk x 64 keys)
#define FL_SZ 32768

// ---------------------------------------------------------------------------
// flash: fused scores+softmax+pv, all fp16 MMA, register-P.
// warp = 16 rows x 64 keys. grid (16, BH), 256 threads.
// ---------------------------------------------------------------------------
__global__ __launch_bounds__(256, 2) void flash_kernel()
{
    extern __shared__ char sm[];
    const uint32_t smb = smem_u32(sm);

    const int bh = blockIdx.y;
    const int m0 = blockIdx.x * 128;
    const size_t qoff = (size_t)bh * S_ * DK;
    const size_t voff = (size_t)bh * DK * S_;

    const int tid  = threadIdx.x;
    const int lane = tid & 31;
    const int wid  = tid >> 5;
    const int g    = lane >> 2;
    const int tq   = lane & 3;

    const int rA  = wid * 16 + (lane & 15);
    const int cA  = (lane >> 4) << 4;
    const int rB0 = (lane & 7) + ((lane & 16) >> 1);
    const int cB  = (lane & 8) << 1;

    auto issueK = [&](int n0) {
#pragma unroll
        for (int i = 0; i < 2; i++) {
            int e = (tid + (i << 8)) << 3;
            int row = e >> 6, col = e & 63;
            uint32_t sw = SWZ((uint32_t)(row * 128 + col * 2));
            cpa16(smb + FK + sw, g_k16 + qoff + (size_t)(n0 + row) * DK + col);
        }
    };
    auto issueV = [&](int n0) {
#pragma unroll
        for (int i = 0; i < 2; i++) {
            int e = (tid + (i << 8)) << 3;
            int row = e >> 6, col = e & 63;     // row = dk, col = key
            uint32_t sw = SWZ((uint32_t)(row * 128 + col * 2));
            cpa16(smb + FV + sw, g_vT16 + voff + (size_t)row * S_ + n0 + col);
        }
    };

    // ---- issue Q (persistent) + K chunk 0 ----
#pragma unroll
    for (int i = 0; i < 4; i++) {
        int e = (tid + (i << 8)) << 3;
        int row = e >> 6, col = e & 63;
        uint32_t sw = SWZ((uint32_t)(row * 128 + col * 2));
        cpa16(smb + FQ + sw, g_q16 + qoff + (size_t)(m0 + row) * DK + col);
    }
    issueK(0);
    CP_COMMIT();

    float acc_o[8][4];
#pragma unroll
    for (int j = 0; j < 8; j++)
#pragma unroll
        for (int q = 0; q < 4; q++) acc_o[j][q] = 0.f;
    float m0r = -1e30f, m1r = -1e30f, s0r = 0.f, s1r = 0.f;

    for (int ch = 0; ch < S_ / 64; ch++) {
        const int n0 = ch << 6;

        CP_WAIT0();
        __syncthreads();                 // K(ch)+Q visible; all warps done with V(ch-1)
        issueV(n0); CP_COMMIT();         // V(ch) flies during S + softmax

        // ---- S = q k^T, single-pass fp16 (q pre-scaled) ----
        float s[8][4];
#pragma unroll
        for (int j = 0; j < 8; j++)
#pragma unroll
            for (int q = 0; q < 4; q++) s[j][q] = 0.f;
#pragma unroll
        for (int ks = 0; ks < 4; ks++) {
            uint32_t a[4];
            ldsm4(a, smb + FQ + SWZ((uint32_t)(rA * 128 + cA + ks * 32)));
            uint32_t b[4][4];
#pragma unroll
            for (int nb = 0; nb < 4; nb++)
                ldsm4(b[nb], smb + FK + SWZ((uint32_t)((rB0 + 16 * nb) * 128 + cB + ks * 32)));
#pragma unroll
            for (int j = 0; j < 8; j++) {
                uint32_t bb[2] = { b[j >> 1][(j & 1) * 2], b[j >> 1][(j & 1) * 2 + 1] };
                hmma_f16(s[j], a, bb);
            }
        }

        // ---- online softmax, fully in registers (rows g and g+8) ----
        float mx0 = -1e30f, mx1 = -1e30f;
#pragma unroll
        for (int j = 0; j < 8; j++) {
            mx0 = fmaxf(mx0, fmaxf(s[j][0], s[j][1]));
            mx1 = fmaxf(mx1, fmaxf(s[j][2], s[j][3]));
        }
        mx0 = fmaxf(mx0, __shfl_xor_sync(~0u, mx0, 1));
        mx0 = fmaxf(mx0, __shfl_xor_sync(~0u, mx0, 2));
        mx1 = fmaxf(mx1, __shfl_xor_sync(~0u, mx1, 1));
        mx1 = fmaxf(mx1, __shfl_xor_sync(~0u, mx1, 2));

        const float mn0 = fmaxf(m0r, mx0), mn1 = fmaxf(m1r, mx1);
        const float al0 = __expf(m0r - mn0), al1 = __expf(m1r - mn1);
        m0r = mn0; m1r = mn1;

        float ps0 = 0.f, ps1 = 0.f;
#pragma unroll
        for (int j = 0; j < 8; j++) {
            s[j][0] = __expf(s[j][0] - mn0);
            s[j][1] = __expf(s[j][1] - mn0);
            s[j][2] = __expf(s[j][2] - mn1);
            s[j][3] = __expf(s[j][3] - mn1);
            ps0 += s[j][0] + s[j][1];
            ps1 += s[j][2] + s[j][3];
            acc_o[j][0] *= al0; acc_o[j][1] *= al0;
            acc_o[j][2] *= al1; acc_o[j][3] *= al1;
        }
        ps0 += __shfl_xor_sync(~0u, ps0, 1);
        ps0 += __shfl_xor_sync(~0u, ps0, 2);
        ps1 += __shfl_xor_sync(~0u, ps1, 1);
        ps1 += __shfl_xor_sync(~0u, ps1, 2);
        s0r = s0r * al0 + ps0;
        s1r = s1r * al1 + ps1;

        CP_WAIT0();
        __syncthreads();                 // V(ch) visible; all warps done with K(ch)
        if (ch + 1 < S_ / 64) { issueK(n0 + 64); CP_COMMIT(); }  // K(ch+1) flies during PV

        // ---- O += P @ V, single-pass fp16, P packed from registers ----
#pragma unroll
        for (int ks = 0; ks < 4; ks++) {
            uint32_t a[4];
            a[0] = pkh2(s[2 * ks][0],     s[2 * ks][1]);
            a[1] = pkh2(s[2 * ks][2],     s[2 * ks][3]);
            a[2] = pkh2(s[2 * ks + 1][0], s[2 * ks + 1][1]);
            a[3] = pkh2(s[2 * ks + 1][2], s[2 * ks + 1][3]);
            uint32_t v[4][4];
#pragma unroll
            for (int nb = 0; nb < 4; nb++)
                ldsm4(v[nb], smb + FV + SWZ((uint32_t)((rB0 + 16 * nb) * 128 + cB + ks * 32)));
#pragma unroll
            for (int j = 0; j < 8; j++) {
                uint32_t bb[2] = { v[j >> 1][(j & 1) * 2], v[j >> 1][(j & 1) * 2 + 1] };
                hmma_f16(acc_o[j], a, bb);
            }
        }
    }

    // ---- epilogue: normalize, split fp16 hi/lo, write ctx ----
    const int b = bh >> 4, h = bh & 15;
    const float inv0 = 1.0f / s0r, inv1 = 1.0f / s1r;
    const int r0 = m0 + wid * 16 + g;
    const size_t ro0 = ((size_t)(b * S_ + r0)) * DM + h * DK;
    const size_t ro1 = ro0 + (size_t)8 * DM;
#pragma unroll
    for (int j = 0; j < 8; j++) {
        const int d = 8 * j + 2 * tq;
        __half h0, l0, h1, l1;
        split2h(acc_o[j][0] * inv0, h0, l0); split2h(acc_o[j][1] * inv0, h1, l1);
        *(uint32_t*)&g_ctxh16[ro0 + d] = pkraw(h0, h1);
        *(uint32_t*)&g_ctxl16[ro0 + d] = pkraw(l0, l1);
        split2h(acc_o[j][2] * inv1, h0, l0); split2h(acc_o[j][3] * inv1, h1, l1);
        *(uint32_t*)&g_ctxh16[ro1 + d] = pkraw(h0, h1);
        *(uint32_t*)&g_ctxl16[ro1 + d] = pkraw(l0, l1);
    }
}

// ---------------------------------------------------------------------------
// out: out = ctx @ Wo^T + bo.  grid (16, 32)
// ---------------------------------------------------------------------------
__global__ __launch_bounds__(256) void out_kernel(float* __restrict__ out,
                                                  const float* __restrict__ bo)
{
    extern __shared__ char sm[];
    const int n0 = blockIdx.x * 64;
    const int m0 = blockIdx.y * 128;

    float acc[2][4][4];
#pragma unroll
    for (int i = 0; i < 2; i++)
#pragma unroll
        for (int j = 0; j < 4; j++)
#pragma unroll
            for (int q = 0; q < 4; q++) acc[i][j][q] = 0.f;

    mma_loop(g_ctxh16 + (size_t)m0 * DM, g_ctxl16 + (size_t)m0 * DM, DM,
             g_Wo16 + (size_t)n0 * DM, DM, DM, sm, acc);

    const int lane = threadIdx.x & 31, wid = threadIdx.x >> 5;
    const int wm = wid >> 1, wn = wid & 1;
#pragma unroll
    for (int i = 0; i < 2; i++)
#pragma unroll
    for (int half = 0; half < 2; half++) {
        const int r = m0 + wm * 32 + i * 16 + (lane >> 2) + half * 8;
#pragma unroll
        for (int j = 0; j < 4; j++) {
            const int c = n0 + wn * 32 + j * 8 + 2 * (lane & 3);
            float2 o = { acc[i][j][half * 2] + bo[c],
                         acc[i][j][half * 2 + 1] + bo[c + 1] };
            *(float2*)(out + (size_t)r * DM + c) = o;
        }
    }
}

// ---------------------------------------------------------------------------
// launcher — no __device__ symbol referenced from host code.
// ---------------------------------------------------------------------------
extern "C" void kernel_launch(void* const* d_in, const int* in_sizes, int n_in,
                              void* d_out, int out_size)
{
    (void)in_sizes; (void)n_in; (void)out_size;
    const float* Q  = (const float*)d_in[0];
    const float* K  = (const float*)d_in[1];
    const float* V  = (const float*)d_in[2];
    const float* bq = (const float*)d_in[4];
    const float* bk = (const float*)d_in[6];
    const float* bv = (const float*)d_in[8];
    const float* bo = (const float*)d_in[10];
    float* out = (float*)d_out;

    cudaFuncSetAttribute(proj_kernel,  cudaFuncAttributeMaxDynamicSharedMemorySize, GE_SZ);
    cudaFuncSetAttribute(out_kernel,   cudaFuncAttributeMaxDynamicSharedMemorySize, GE_SZ);
    cudaFuncSetAttribute(flash_kernel, cudaFuncAttributeMaxDynamicSharedMemorySize, FL_SZ);

    const int total4 = 3 * NX4 + 4 * NW4;
    cvt_kernel<<<total4 / 256, 256>>>(Q, K, V,
                                      (const float*)d_in[3], (const float*)d_in[5],
                                      (const float*)d_in[7], (const float*)d_in[9]);

    proj_kernel <<<dim3(DM / 64, MROWS / 128, 3), 256, GE_SZ>>>(bq, bk, bv);
    flash_kernel<<<dim3(S_ / 128, BH), 256, FL_SZ>>>();
    out_kernel  <<<dim3(DM / 64, MROWS / 128),    256, GE_SZ>>>(out, bo);
}

// round 12
// speedup vs baseline: 8.9256x; 1.3437x over previous
#include <cuda_runtime.h>
#include <cuda_bf16.h>
#include <cuda_fp16.h>
#include <cstdint>

// ===========================================================================
// MHA  B=2 S=2048 DM=1024 H=16 DK=64 — Round 11: single-pass fp16 everywhere
//   proj/out: 1-pass fp16 GEMM (A fp16, B fp16), 2-stage cp.async pipeline
//   flash   : single-pass fp16 S + PV, register P (unchanged from R10)
// ===========================================================================

#define B_    2
#define S_    2048
#define H_    16
#define DK    64
#define DM    1024
#define MROWS (B_ * S_)   // 4096
#define BH    (B_ * H_)   // 32

typedef unsigned short u16;

// ---------------- device scratch ----------------
__device__ u16 g_Q16[MROWS * DM], g_K16in[MROWS * DM], g_V16[MROWS * DM];
__device__ u16 g_Wq16[DM * DM], g_Wk16[DM * DM], g_Wv16[DM * DM], g_Wo16[DM * DM];
__device__ u16 g_q16[BH * S_ * DK];            // fp16, pre-scaled by 0.125
__device__ u16 g_k16[BH * S_ * DK];
__device__ u16 g_vT16[BH * DK * S_];           // transposed V
__device__ u16 g_ctx16[MROWS * DM];

// ---------------- helpers ----------------
__device__ __forceinline__ uint32_t smem_u32(const void* p) {
    uint32_t a;
    asm("{ .reg .u64 t; cvta.to.shared.u64 t, %1; cvt.u32.u64 %0, t; }" : "=r"(a) : "l"(p));
    return a;
}
#define SWZ(b) ((b) ^ (((b) >> 3) & 0x70))

__device__ __forceinline__ void ldsm4(uint32_t r[4], uint32_t addr) {
    asm volatile("ldmatrix.sync.aligned.m8n8.x4.shared.b16 {%0,%1,%2,%3}, [%4];"
        : "=r"(r[0]), "=r"(r[1]), "=r"(r[2]), "=r"(r[3]) : "r"(addr));
}
__device__ __forceinline__ void cpa16(uint32_t dst, const void* src) {
    asm volatile("cp.async.cg.shared.global [%0], [%1], 16;" :: "r"(dst), "l"(src) : "memory");
}
#define CP_COMMIT() asm volatile("cp.async.commit_group;" ::: "memory")
#define CP_WAIT0()  asm volatile("cp.async.wait_group 0;" ::: "memory")

__device__ __forceinline__ void hmma_f16(float c[4], const uint32_t a[4], const uint32_t b[2]) {
    asm volatile("mma.sync.aligned.m16n8k16.row.col.f32.f16.f16.f32 "
        "{%0,%1,%2,%3}, {%4,%5,%6,%7}, {%8,%9}, {%0,%1,%2,%3};"
        : "+f"(c[0]), "+f"(c[1]), "+f"(c[2]), "+f"(c[3])
        : "r"(a[0]), "r"(a[1]), "r"(a[2]), "r"(a[3]), "r"(b[0]), "r"(b[1]));
}
__device__ __forceinline__ uint32_t pkh2(float a, float b) {
    __half2 h2 = __floats2half2_rn(a, b);
    return *(uint32_t*)&h2;
}

// ---------------- proj/out pipelined smem: 2 stages x 24 KB ----------------
#define STG_A  0
#define STG_B  16384
#define STG_SZ 24576
#define GE_SZ  (2 * STG_SZ)   // 48 KB dynamic

// ---------------------------------------------------------------------------
// one 64-deep k-tile of fp16 MMAs for the 4x2-warp GEMM kernels
// ---------------------------------------------------------------------------
__device__ __forceinline__ void mma_tile64(
    uint32_t Ab, uint32_t Bb, int rA, int cA, int rB, int cB, float acc[2][4][4])
{
#pragma unroll
    for (int ks = 0; ks < 4; ks++) {
        uint32_t a[2][4], b0[4], b1[4];
        ldsm4(a[0], Ab + SWZ((uint32_t)((rA)      * 128 + cA + ks * 32)));
        ldsm4(a[1], Ab + SWZ((uint32_t)((rA + 16) * 128 + cA + ks * 32)));
        ldsm4(b0,   Bb + SWZ((uint32_t)((rB)      * 128 + cB + ks * 32)));
        ldsm4(b1,   Bb + SWZ((uint32_t)((rB + 16) * 128 + cB + ks * 32)));
        uint32_t bb[4][2] = { {b0[0],b0[1]}, {b0[2],b0[3]},
                              {b1[0],b1[1]}, {b1[2],b1[3]} };
#pragma unroll
        for (int i = 0; i < 2; i++)
#pragma unroll
            for (int j = 0; j < 4; j++)
                hmma_f16(acc[i][j], a[i], bb[j]);
    }
}

// ---------------------------------------------------------------------------
// GEMM mainloop (proj/out): 2-stage cp.async pipeline, single-pass fp16.
// ---------------------------------------------------------------------------
__device__ __forceinline__ void mma_loop(
    const u16* __restrict__ Ap, int lda,
    const u16* __restrict__ Bp, int ldb,
    int K, char* sm, float acc[2][4][4])
{
    const int tid  = threadIdx.x;
    const int lane = tid & 31;
    const int wid  = tid >> 5;
    const int wm   = wid >> 1;
    const int wn   = wid & 1;
    const uint32_t smb = smem_u32(sm);

    const int rA = wm * 32 + (lane & 15);
    const int cA = (lane >> 4) << 4;
    const int rB = wn * 32 + (lane & 7) + ((lane & 16) >> 1);
    const int cB = (lane & 8) << 1;

    auto issue = [&](int ch, uint32_t st) {
        const int k0 = ch << 6;
#pragma unroll
        for (int i = 0; i < 4; i++) {
            int e = (tid + (i << 8)) << 3;
            int row = e >> 6, col = e & 63;
            uint32_t sw = SWZ((uint32_t)(row * 128 + col * 2));
            cpa16(st + STG_A + sw, Ap + (size_t)row * lda + k0 + col);
        }
#pragma unroll
        for (int i = 0; i < 2; i++) {
            int e = (tid + (i << 8)) << 3;
            int row = e >> 6, col = e & 63;
            uint32_t sw = SWZ((uint32_t)(row * 128 + col * 2));
            cpa16(st + STG_B + sw, Bp + (size_t)row * ldb + k0 + col);
        }
    };

    const int nch = K >> 6;
    issue(0, smb); CP_COMMIT();
    for (int ch = 0; ch < nch; ch++) {
        CP_WAIT0();
        __syncthreads();
        if (ch + 1 < nch) { issue(ch + 1, smb + ((ch + 1) & 1) * STG_SZ); CP_COMMIT(); }
        const uint32_t st = smb + (ch & 1) * STG_SZ;
        mma_tile64(st + STG_A, st + STG_B, rA, cA, rB, cB, acc);
    }
}

// ---------------------------------------------------------------------------
// cvt (merged): all 7 fp32 tensors -> single fp16. One launch.
// ---------------------------------------------------------------------------
#define NX4 (MROWS * DM / 4)   // 1M quads per X tensor
#define NW4 (DM * DM / 4)      // 256K quads per W tensor
__global__ void cvt_kernel(const float* __restrict__ Q, const float* __restrict__ K,
                           const float* __restrict__ V, const float* __restrict__ Wq,
                           const float* __restrict__ Wk, const float* __restrict__ Wv,
                           const float* __restrict__ Wo)
{
    int i = blockIdx.x * blockDim.x + threadIdx.x;
    const float* src; u16* dst; int off;
    if (i < NX4)          { src = Q;  dst = g_Q16;   off = i; }
    else if (i < 2 * NX4) { src = K;  dst = g_K16in; off = i - NX4; }
    else if (i < 3 * NX4) { src = V;  dst = g_V16;   off = i - 2 * NX4; }
    else {
        int w = i - 3 * NX4;
        int t = w / NW4; off = w - t * NW4;
        if (t == 0)      { src = Wq; dst = g_Wq16; }
        else if (t == 1) { src = Wk; dst = g_Wk16; }
        else if (t == 2) { src = Wv; dst = g_Wv16; }
        else             { src = Wo; dst = g_Wo16; }
    }
    float4 v = ((const float4*)src)[off];
    ((uint2*)dst)[off] = make_uint2(pkh2(v.x, v.y), pkh2(v.z, v.w));
}

// ---------------------------------------------------------------------------
// proj: z=0 -> q (fp16, x0.125), z=1 -> k, z=2 -> vT. grid (16, 32, 3)
// ---------------------------------------------------------------------------
__global__ __launch_bounds__(256) void proj_kernel(
    const float* __restrict__ bq, const float* __restrict__ bk,
    const float* __restrict__ bv)
{
    extern __shared__ char sm[];
    const int z  = blockIdx.z;
    const int n0 = blockIdx.x * 64;
    const int m0 = blockIdx.y * 128;

    const u16 *Ap, *Bp;
    const float* bias;
    if (z == 0)      { Ap = g_Q16;   Bp = g_Wq16; bias = bq; }
    else if (z == 1) { Ap = g_K16in; Bp = g_Wk16; bias = bk; }
    else             { Ap = g_V16;   Bp = g_Wv16; bias = bv; }

    float acc[2][4][4];
#pragma unroll
    for (int i = 0; i < 2; i++)
#pragma unroll
        for (int j = 0; j < 4; j++)
#pragma unroll
            for (int q = 0; q < 4; q++) acc[i][j][q] = 0.f;

    mma_loop(Ap + (size_t)m0 * DM, DM, Bp + (size_t)n0 * DM, DM, DM, sm, acc);

    const int lane = threadIdx.x & 31, wid = threadIdx.x >> 5;
    const int wm = wid >> 1, wn = wid & 1;
#pragma unroll
    for (int i = 0; i < 2; i++)
#pragma unroll
    for (int half = 0; half < 2; half++) {
        const int r = m0 + wm * 32 + i * 16 + (lane >> 2) + half * 8;
        const int b = r >> 11, s = r & (S_ - 1);
#pragma unroll
        for (int j = 0; j < 4; j++) {
            const int n = n0 + wn * 32 + j * 8 + 2 * (lane & 3);
            float v0 = acc[i][j][half * 2]     + bias[n];
            float v1 = acc[i][j][half * 2 + 1] + bias[n + 1];
            const int hh = n >> 6, dk = n & 63;
            const size_t bh = (size_t)(b * H_ + hh);
            if (z == 0) {
                *(uint32_t*)&g_q16[(bh * S_ + s) * DK + dk] = pkh2(v0 * 0.125f, v1 * 0.125f);
            } else if (z == 1) {
                *(uint32_t*)&g_k16[(bh * S_ + s) * DK + dk] = pkh2(v0, v1);
            } else {
                __half h0 = __float2half_rn(v0), h1 = __float2half_rn(v1);
                g_vT16[(bh * DK + dk)     * S_ + s] = *(u16*)&h0;
                g_vT16[(bh * DK + dk + 1) * S_ + s] = *(u16*)&h1;
            }
        }
    }
}

// ---------------- flash smem layout (dynamic, 32 KB) ----------------
#define FQ  0          // 16 KB fp16 q tile (128 x 64)
#define FK  16384      // 8 KB  fp16 K chunk (64 x 64)
#define FV  24576      // 8 KB  fp16 vT chunk (64 dk x 64 keys)
#define FL_SZ 32768

// ---------------------------------------------------------------------------
// flash: fused scores+softmax+pv, all fp16 MMA, register-P.
// warp = 16 rows x 64 keys. grid (16, BH), 256 threads.
// ---------------------------------------------------------------------------
__global__ __launch_bounds__(256, 2) void flash_kernel()
{
    extern __shared__ char sm[];
    const uint32_t smb = smem_u32(sm);

    const int bh = blockIdx.y;
    const int m0 = blockIdx.x * 128;
    const size_t qoff = (size_t)bh * S_ * DK;
    const size_t voff = (size_t)bh * DK * S_;

    const int tid  = threadIdx.x;
    const int lane = tid & 31;
    const int wid  = tid >> 5;
    const int g    = lane >> 2;
    const int tq   = lane & 3;

    const int rA  = wid * 16 + (lane & 15);
    const int cA  = (lane >> 4) << 4;
    const int rB0 = (lane & 7) + ((lane & 16) >> 1);
    const int cB  = (lane & 8) << 1;

    auto issueK = [&](int n0) {
#pragma unroll
        for (int i = 0; i < 2; i++) {
            int e = (tid + (i << 8)) << 3;
            int row = e >> 6, col = e & 63;
            uint32_t sw = SWZ((uint32_t)(row * 128 + col * 2));
            cpa16(smb + FK + sw, g_k16 + qoff + (size_t)(n0 + row) * DK + col);
        }
    };
    auto issueV = [&](int n0) {
#pragma unroll
        for (int i = 0; i < 2; i++) {
            int e = (tid + (i << 8)) << 3;
            int row = e >> 6, col = e & 63;     // row = dk, col = key
            uint32_t sw = SWZ((uint32_t)(row * 128 + col * 2));
            cpa16(smb + FV + sw, g_vT16 + voff + (size_t)row * S_ + n0 + col);
        }
    };

    // ---- issue Q (persistent) + K chunk 0 ----
#pragma unroll
    for (int i = 0; i < 4; i++) {
        int e = (tid + (i << 8)) << 3;
        int row = e >> 6, col = e & 63;
        uint32_t sw = SWZ((uint32_t)(row * 128 + col * 2));
        cpa16(smb + FQ + sw, g_q16 + qoff + (size_t)(m0 + row) * DK + col);
    }
    issueK(0);
    CP_COMMIT();

    float acc_o[8][4];
#pragma unroll
    for (int j = 0; j < 8; j++)
#pragma unroll
        for (int q = 0; q < 4; q++) acc_o[j][q] = 0.f;
    float m0r = -1e30f, m1r = -1e30f, s0r = 0.f, s1r = 0.f;

    for (int ch = 0; ch < S_ / 64; ch++) {
        const int n0 = ch << 6;

        CP_WAIT0();
        __syncthreads();                 // K(ch)+Q visible; all warps done with V(ch-1)
        issueV(n0); CP_COMMIT();         // V(ch) flies during S + softmax

        // ---- S = q k^T, single-pass fp16 (q pre-scaled) ----
        float s[8][4];
#pragma unroll
        for (int j = 0; j < 8; j++)
#pragma unroll
            for (int q = 0; q < 4; q++) s[j][q] = 0.f;
#pragma unroll
        for (int ks = 0; ks < 4; ks++) {
            uint32_t a[4];
            ldsm4(a, smb + FQ + SWZ((uint32_t)(rA * 128 + cA + ks * 32)));
            uint32_t b[4][4];
#pragma unroll
            for (int nb = 0; nb < 4; nb++)
                ldsm4(b[nb], smb + FK + SWZ((uint32_t)((rB0 + 16 * nb) * 128 + cB + ks * 32)));
#pragma unroll
            for (int j = 0; j < 8; j++) {
                uint32_t bb[2] = { b[j >> 1][(j & 1) * 2], b[j >> 1][(j & 1) * 2 + 1] };
                hmma_f16(s[j], a, bb);
            }
        }

        // ---- online softmax, fully in registers (rows g and g+8) ----
        float mx0 = -1e30f, mx1 = -1e30f;
#pragma unroll
        for (int j = 0; j < 8; j++) {
            mx0 = fmaxf(mx0, fmaxf(s[j][0], s[j][1]));
            mx1 = fmaxf(mx1, fmaxf(s[j][2], s[j][3]));
        }
        mx0 = fmaxf(mx0, __shfl_xor_sync(~0u, mx0, 1));
        mx0 = fmaxf(mx0, __shfl_xor_sync(~0u, mx0, 2));
        mx1 = fmaxf(mx1, __shfl_xor_sync(~0u, mx1, 1));
        mx1 = fmaxf(mx1, __shfl_xor_sync(~0u, mx1, 2));

        const float mn0 = fmaxf(m0r, mx0), mn1 = fmaxf(m1r, mx1);
        const float al0 = __expf(m0r - mn0), al1 = __expf(m1r - mn1);
        m0r = mn0; m1r = mn1;

        float ps0 = 0.f, ps1 = 0.f;
#pragma unroll
        for (int j = 0; j < 8; j++) {
            s[j][0] = __expf(s[j][0] - mn0);
            s[j][1] = __expf(s[j][1] - mn0);
            s[j][2] = __expf(s[j][2] - mn1);
            s[j][3] = __expf(s[j][3] - mn1);
            ps0 += s[j][0] + s[j][1];
            ps1 += s[j][2] + s[j][3];
            acc_o[j][0] *= al0; acc_o[j][1] *= al0;
            acc_o[j][2] *= al1; acc_o[j][3] *= al1;
        }
        ps0 += __shfl_xor_sync(~0u, ps0, 1);
        ps0 += __shfl_xor_sync(~0u, ps0, 2);
        ps1 += __shfl_xor_sync(~0u, ps1, 1);
        ps1 += __shfl_xor_sync(~0u, ps1, 2);
        s0r = s0r * al0 + ps0;
        s1r = s1r * al1 + ps1;

        CP_WAIT0();
        __syncthreads();                 // V(ch) visible; all warps done with K(ch)
        if (ch + 1 < S_ / 64) { issueK(n0 + 64); CP_COMMIT(); }  // K(ch+1) flies during PV

        // ---- O += P @ V, single-pass fp16, P packed from registers ----
#pragma unroll
        for (int ks = 0; ks < 4; ks++) {
            uint32_t a[4];
            a[0] = pkh2(s[2 * ks][0],     s[2 * ks][1]);
            a[1] = pkh2(s[2 * ks][2],     s[2 * ks][3]);
            a[2] = pkh2(s[2 * ks + 1][0], s[2 * ks + 1][1]);
            a[3] = pkh2(s[2 * ks + 1][2], s[2 * ks + 1][3]);
            uint32_t v[4][4];
#pragma unroll
            for (int nb = 0; nb < 4; nb++)
                ldsm4(v[nb], smb + FV + SWZ((uint32_t)((rB0 + 16 * nb) * 128 + cB + ks * 32)));
#pragma unroll
            for (int j = 0; j < 8; j++) {
                uint32_t bb[2] = { v[j >> 1][(j & 1) * 2], v[j >> 1][(j & 1) * 2 + 1] };
                hmma_f16(acc_o[j], a, bb);
            }
        }
    }

    // ---- epilogue: normalize, write ctx (single fp16) ----
    const int b = bh >> 4, h = bh & 15;
    const float inv0 = 1.0f / s0r, inv1 = 1.0f / s1r;
    const int r0 = m0 + wid * 16 + g;
    const size_t ro0 = ((size_t)(b * S_ + r0)) * DM + h * DK;
    const size_t ro1 = ro0 + (size_t)8 * DM;
#pragma unroll
    for (int j = 0; j < 8; j++) {
        const int d = 8 * j + 2 * tq;
        *(uint32_t*)&g_ctx16[ro0 + d] = pkh2(acc_o[j][0] * inv0, acc_o[j][1] * inv0);
        *(uint32_t*)&g_ctx16[ro1 + d] = pkh2(acc_o[j][2] * inv1, acc_o[j][3] * inv1);
    }
}

// ---------------------------------------------------------------------------
// out: out = ctx @ Wo^T + bo.  grid (16, 32)
// ---------------------------------------------------------------------------
__global__ __launch_bounds__(256) void out_kernel(float* __restrict__ out,
                                                  const float* __restrict__ bo)
{
    extern __shared__ char sm[];
    const int n0 = blockIdx.x * 64;
    const int m0 = blockIdx.y * 128;

    float acc[2][4][4];
#pragma unroll
    for (int i = 0; i < 2; i++)
#pragma unroll
        for (int j = 0; j < 4; j++)
#pragma unroll
            for (int q = 0; q < 4; q++) acc[i][j][q] = 0.f;

    mma_loop(g_ctx16 + (size_t)m0 * DM, DM, g_Wo16 + (size_t)n0 * DM, DM, DM, sm, acc);

    const int lane = threadIdx.x & 31, wid = threadIdx.x >> 5;
    const int wm = wid >> 1, wn = wid & 1;
#pragma unroll
    for (int i = 0; i < 2; i++)
#pragma unroll
    for (int half = 0; half < 2; half++) {
        const int r = m0 + wm * 32 + i * 16 + (lane >> 2) + half * 8;
#pragma unroll
        for (int j = 0; j < 4; j++) {
            const int c = n0 + wn * 32 + j * 8 + 2 * (lane & 3);
            float2 o = { acc[i][j][half * 2] + bo[c],
                         acc[i][j][half * 2 + 1] + bo[c + 1] };
            *(float2*)(out + (size_t)r * DM + c) = o;
        }
    }
}

// ---------------------------------------------------------------------------
// launcher — no __device__ symbol referenced from host code.
// ---------------------------------------------------------------------------
extern "C" void kernel_launch(void* const* d_in, const int* in_sizes, int n_in,
                              void* d_out, int out_size)
{
    (void)in_sizes; (void)n_in; (void)out_size;
    const float* Q  = (const float*)d_in[0];
    const float* K  = (const float*)d_in[1];
    const float* V  = (const float*)d_in[2];
    const float* bq = (const float*)d_in[4];
    const float* bk = (const float*)d_in[6];
    const float* bv = (const float*)d_in[8];
    const float* bo = (const float*)d_in[10];
    float* out = (float*)d_out;

    cudaFuncSetAttribute(proj_kernel,  cudaFuncAttributeMaxDynamicSharedMemorySize, GE_SZ);
    cudaFuncSetAttribute(out_kernel,   cudaFuncAttributeMaxDynamicSharedMemorySize, GE_SZ);
    cudaFuncSetAttribute(flash_kernel, cudaFuncAttributeMaxDynamicSharedMemorySize, FL_SZ);

    const int total4 = 3 * NX4 + 4 * NW4;
    cvt_kernel<<<total4 / 256, 256>>>(Q, K, V,
                                      (const float*)d_in[3], (const float*)d_in[5],
                                      (const float*)d_in[7], (const float*)d_in[9]);

    proj_kernel <<<dim3(DM / 64, MROWS / 128, 3), 256, GE_SZ>>>(bq, bk, bv);
    flash_kernel<<<dim3(S_ / 128, BH), 256, FL_SZ>>>();
    out_kernel  <<<dim3(DM / 64, MROWS / 128),    256, GE_SZ>>>(out, bo);
}

// round 13
// speedup vs baseline: 9.1134x; 1.0210x over previous
#include <cuda_runtime.h>
#include <cuda_bf16.h>
#include <cuda_fp16.h>
#include <cstdint>

// ===========================================================================
// MHA  B=2 S=2048 DM=1024 H=16 DK=64 — Round 12:
//   proj/out: 128x128 block tile (warp 32x64), 1-pass fp16, 2-stage cp.async
//   flash   : unchanged (single-pass fp16 S + PV, register P)
// ===========================================================================

#define B_    2
#define S_    2048
#define H_    16
#define DK    64
#define DM    1024
#define MROWS (B_ * S_)   // 4096
#define BH    (B_ * H_)   // 32

typedef unsigned short u16;

// ---------------- device scratch ----------------
__device__ u16 g_Q16[MROWS * DM], g_K16in[MROWS * DM], g_V16[MROWS * DM];
__device__ u16 g_Wq16[DM * DM], g_Wk16[DM * DM], g_Wv16[DM * DM], g_Wo16[DM * DM];
__device__ u16 g_q16[BH * S_ * DK];            // fp16, pre-scaled by 0.125
__device__ u16 g_k16[BH * S_ * DK];
__device__ u16 g_vT16[BH * DK * S_];           // transposed V
__device__ u16 g_ctx16[MROWS * DM];

// ---------------- helpers ----------------
__device__ __forceinline__ uint32_t smem_u32(const void* p) {
    uint32_t a;
    asm("{ .reg .u64 t; cvta.to.shared.u64 t, %1; cvt.u32.u64 %0, t; }" : "=r"(a) : "l"(p));
    return a;
}
#define SWZ(b) ((b) ^ (((b) >> 3) & 0x70))

__device__ __forceinline__ void ldsm4(uint32_t r[4], uint32_t addr) {
    asm volatile("ldmatrix.sync.aligned.m8n8.x4.shared.b16 {%0,%1,%2,%3}, [%4];"
        : "=r"(r[0]), "=r"(r[1]), "=r"(r[2]), "=r"(r[3]) : "r"(addr));
}
__device__ __forceinline__ void cpa16(uint32_t dst, const void* src) {
    asm volatile("cp.async.cg.shared.global [%0], [%1], 16;" :: "r"(dst), "l"(src) : "memory");
}
#define CP_COMMIT() asm volatile("cp.async.commit_group;" ::: "memory")
#define CP_WAIT0()  asm volatile("cp.async.wait_group 0;" ::: "memory")

__device__ __forceinline__ void hmma_f16(float c[4], const uint32_t a[4], const uint32_t b[2]) {
    asm volatile("mma.sync.aligned.m16n8k16.row.col.f32.f16.f16.f32 "
        "{%0,%1,%2,%3}, {%4,%5,%6,%7}, {%8,%9}, {%0,%1,%2,%3};"
        : "+f"(c[0]), "+f"(c[1]), "+f"(c[2]), "+f"(c[3])
        : "r"(a[0]), "r"(a[1]), "r"(a[2]), "r"(a[3]), "r"(b[0]), "r"(b[1]));
}
__device__ __forceinline__ uint32_t pkh2(float a, float b) {
    __half2 h2 = __floats2half2_rn(a, b);
    return *(uint32_t*)&h2;
}

// ---------------- proj/out pipelined smem: 2 stages x 32 KB ----------------
// A: 128 x 64 fp16 (16 KB), B: 128 x 64 fp16 (16 KB)
#define STG_A  0
#define STG_B  16384
#define STG_SZ 32768
#define GE_SZ  (2 * STG_SZ)   // 64 KB dynamic

// ---------------------------------------------------------------------------
// GEMM mainloop: block 128(M) x 128(N), warp tile 32x64, 2-stage cp.async.
// acc[2][8][4]: i = m-subtile (16 rows), j = n-subtile (8 cols).
// ---------------------------------------------------------------------------
__device__ __forceinline__ void mma_loop(
    const u16* __restrict__ Ap, int lda,
    const u16* __restrict__ Bp, int ldb,
    int K, char* sm, float acc[2][8][4])
{
    const int tid  = threadIdx.x;
    const int lane = tid & 31;
    const int wid  = tid >> 5;
    const int wm   = wid >> 1;       // 0..3 (m)
    const int wn   = wid & 1;        // 0..1 (n, 64-wide)
    const uint32_t smb = smem_u32(sm);

    const int rA  = wm * 32 + (lane & 15);
    const int cA  = (lane >> 4) << 4;
    const int rB0 = wn * 64 + (lane & 7) + ((lane & 16) >> 1);
    const int cB  = (lane & 8) << 1;

    auto issue = [&](int ch, uint32_t st) {
        const int k0 = ch << 6;
#pragma unroll
        for (int i = 0; i < 4; i++) {
            int e = (tid + (i << 8)) << 3;
            int row = e >> 6, col = e & 63;
            uint32_t sw = SWZ((uint32_t)(row * 128 + col * 2));
            cpa16(st + STG_A + sw, Ap + (size_t)row * lda + k0 + col);
            cpa16(st + STG_B + sw, Bp + (size_t)row * ldb + k0 + col);
        }
    };

    const int nch = K >> 6;
    issue(0, smb); CP_COMMIT();
    for (int ch = 0; ch < nch; ch++) {
        CP_WAIT0();
        __syncthreads();
        if (ch + 1 < nch) { issue(ch + 1, smb + ((ch + 1) & 1) * STG_SZ); CP_COMMIT(); }
        const uint32_t st = smb + (ch & 1) * STG_SZ;
#pragma unroll
        for (int ks = 0; ks < 4; ks++) {
            uint32_t a[2][4];
            ldsm4(a[0], st + STG_A + SWZ((uint32_t)((rA)      * 128 + cA + ks * 32)));
            ldsm4(a[1], st + STG_A + SWZ((uint32_t)((rA + 16) * 128 + cA + ks * 32)));
            uint32_t b[4][4];
#pragma unroll
            for (int nb = 0; nb < 4; nb++)
                ldsm4(b[nb], st + STG_B + SWZ((uint32_t)((rB0 + 16 * nb) * 128 + cB + ks * 32)));
#pragma unroll
            for (int i = 0; i < 2; i++)
#pragma unroll
                for (int j = 0; j < 8; j++) {
                    uint32_t bb[2] = { b[j >> 1][(j & 1) * 2], b[j >> 1][(j & 1) * 2 + 1] };
                    hmma_f16(acc[i][j], a[i], bb);
                }
        }
    }
}

// ---------------------------------------------------------------------------
// cvt (merged): all 7 fp32 tensors -> single fp16. One launch.
// ---------------------------------------------------------------------------
#define NX4 (MROWS * DM / 4)
#define NW4 (DM * DM / 4)
__global__ void cvt_kernel(const float* __restrict__ Q, const float* __restrict__ K,
                           const float* __restrict__ V, const float* __restrict__ Wq,
                           const float* __restrict__ Wk, const float* __restrict__ Wv,
                           const float* __restrict__ Wo)
{
    int i = blockIdx.x * blockDim.x + threadIdx.x;
    const float* src; u16* dst; int off;
    if (i < NX4)          { src = Q;  dst = g_Q16;   off = i; }
    else if (i < 2 * NX4) { src = K;  dst = g_K16in; off = i - NX4; }
    else if (i < 3 * NX4) { src = V;  dst = g_V16;   off = i - 2 * NX4; }
    else {
        int w = i - 3 * NX4;
        int t = w / NW4; off = w - t * NW4;
        if (t == 0)      { src = Wq; dst = g_Wq16; }
        else if (t == 1) { src = Wk; dst = g_Wk16; }
        else if (t == 2) { src = Wv; dst = g_Wv16; }
        else             { src = Wo; dst = g_Wo16; }
    }
    float4 v = ((const float4*)src)[off];
    ((uint2*)dst)[off] = make_uint2(pkh2(v.x, v.y), pkh2(v.z, v.w));
}

// ---------------------------------------------------------------------------
// proj: z=0 -> q (fp16, x0.125), z=1 -> k, z=2 -> vT. grid (8, 32, 3)
// ---------------------------------------------------------------------------
__global__ __launch_bounds__(256) void proj_kernel(
    const float* __restrict__ bq, const float* __restrict__ bk,
    const float* __restrict__ bv)
{
    extern __shared__ char sm[];
    const int z  = blockIdx.z;
    const int n0 = blockIdx.x * 128;
    const int m0 = blockIdx.y * 128;

    const u16 *Ap, *Bp;
    const float* bias;
    if (z == 0)      { Ap = g_Q16;   Bp = g_Wq16; bias = bq; }
    else if (z == 1) { Ap = g_K16in; Bp = g_Wk16; bias = bk; }
    else             { Ap = g_V16;   Bp = g_Wv16; bias = bv; }

    float acc[2][8][4];
#pragma unroll
    for (int i = 0; i < 2; i++)
#pragma unroll
        for (int j = 0; j < 8; j++)
#pragma unroll
            for (int q = 0; q < 4; q++) acc[i][j][q] = 0.f;

    mma_loop(Ap + (size_t)m0 * DM, DM, Bp + (size_t)n0 * DM, DM, DM, sm, acc);

    const int lane = threadIdx.x & 31, wid = threadIdx.x >> 5;
    const int wm = wid >> 1, wn = wid & 1;
#pragma unroll
    for (int i = 0; i < 2; i++)
#pragma unroll
    for (int half = 0; half < 2; half++) {
        const int r = m0 + wm * 32 + i * 16 + (lane >> 2) + half * 8;
        const int b = r >> 11, s = r & (S_ - 1);
#pragma unroll
        for (int j = 0; j < 8; j++) {
            const int n = n0 + wn * 64 + j * 8 + 2 * (lane & 3);
            float v0 = acc[i][j][half * 2]     + bias[n];
            float v1 = acc[i][j][half * 2 + 1] + bias[n + 1];
            const int hh = n >> 6, dk = n & 63;
            const size_t bh = (size_t)(b * H_ + hh);
            if (z == 0) {
                *(uint32_t*)&g_q16[(bh * S_ + s) * DK + dk] = pkh2(v0 * 0.125f, v1 * 0.125f);
            } else if (z == 1) {
                *(uint32_t*)&g_k16[(bh * S_ + s) * DK + dk] = pkh2(v0, v1);
            } else {
                __half h0 = __float2half_rn(v0), h1 = __float2half_rn(v1);
                g_vT16[(bh * DK + dk)     * S_ + s] = *(u16*)&h0;
                g_vT16[(bh * DK + dk + 1) * S_ + s] = *(u16*)&h1;
            }
        }
    }
}

// ---------------- flash smem layout (dynamic, 32 KB) ----------------
#define FQ  0          // 16 KB fp16 q tile (128 x 64)
#define FK  16384      // 8 KB  fp16 K chunk (64 x 64)
#define FV  24576      // 8 KB  fp16 vT chunk (64 dk x 64 keys)
#define FL_SZ 32768

// ---------------------------------------------------------------------------
// flash: fused scores+softmax+pv, all fp16 MMA, register-P.
// warp = 16 rows x 64 keys. grid (16, BH), 256 threads.
// ---------------------------------------------------------------------------
__global__ __launch_bounds__(256, 2) void flash_kernel()
{
    extern __shared__ char sm[];
    const uint32_t smb = smem_u32(sm);

    const int bh = blockIdx.y;
    const int m0 = blockIdx.x * 128;
    const size_t qoff = (size_t)bh * S_ * DK;
    const size_t voff = (size_t)bh * DK * S_;

    const int tid  = threadIdx.x;
    const int lane = tid & 31;
    const int wid  = tid >> 5;
    const int g    = lane >> 2;
    const int tq   = lane & 3;

    const int rA  = wid * 16 + (lane & 15);
    const int cA  = (lane >> 4) << 4;
    const int rB0 = (lane & 7) + ((lane & 16) >> 1);
    const int cB  = (lane & 8) << 1;

    auto issueK = [&](int n0) {
#pragma unroll
        for (int i = 0; i < 2; i++) {
            int e = (tid + (i << 8)) << 3;
            int row = e >> 6, col = e & 63;
            uint32_t sw = SWZ((uint32_t)(row * 128 + col * 2));
            cpa16(smb + FK + sw, g_k16 + qoff + (size_t)(n0 + row) * DK + col);
        }
    };
    auto issueV = [&](int n0) {
#pragma unroll
        for (int i = 0; i < 2; i++) {
            int e = (tid + (i << 8)) << 3;
            int row = e >> 6, col = e & 63;     // row = dk, col = key
            uint32_t sw = SWZ((uint32_t)(row * 128 + col * 2));
            cpa16(smb + FV + sw, g_vT16 + voff + (size_t)row * S_ + n0 + col);
        }
    };

    // ---- issue Q (persistent) + K chunk 0 ----
#pragma unroll
    for (int i = 0; i < 4; i++) {
        int e = (tid + (i << 8)) << 3;
        int row = e >> 6, col = e & 63;
        uint32_t sw = SWZ((uint32_t)(row * 128 + col * 2));
        cpa16(smb + FQ + sw, g_q16 + qoff + (size_t)(m0 + row) * DK + col);
    }
    issueK(0);
    CP_COMMIT();

    float acc_o[8][4];
#pragma unroll
    for (int j = 0; j < 8; j++)
#pragma unroll
        for (int q = 0; q < 4; q++) acc_o[j][q] = 0.f;
    float m0r = -1e30f, m1r = -1e30f, s0r = 0.f, s1r = 0.f;

    for (int ch = 0; ch < S_ / 64; ch++) {
        const int n0 = ch << 6;

        CP_WAIT0();
        __syncthreads();                 // K(ch)+Q visible; all warps done with V(ch-1)
        issueV(n0); CP_COMMIT();         // V(ch) flies during S + softmax

        // ---- S = q k^T, single-pass fp16 (q pre-scaled) ----
        float s[8][4];
#pragma unroll
        for (int j = 0; j < 8; j++)
#pragma unroll
            for (int q = 0; q < 4; q++) s[j][q] = 0.f;
#pragma unroll
        for (int ks = 0; ks < 4; ks++) {
            uint32_t a[4];
            ldsm4(a, smb + FQ + SWZ((uint32_t)(rA * 128 + cA + ks * 32)));
            uint32_t b[4][4];
#pragma unroll
            for (int nb = 0; nb < 4; nb++)
                ldsm4(b[nb], smb + FK + SWZ((uint32_t)((rB0 + 16 * nb) * 128 + cB + ks * 32)));
#pragma unroll
            for (int j = 0; j < 8; j++) {
                uint32_t bb[2] = { b[j >> 1][(j & 1) * 2], b[j >> 1][(j & 1) * 2 + 1] };
                hmma_f16(s[j], a, bb);
            }
        }

        // ---- online softmax, fully in registers (rows g and g+8) ----
        float mx0 = -1e30f, mx1 = -1e30f;
#pragma unroll
        for (int j = 0; j < 8; j++) {
            mx0 = fmaxf(mx0, fmaxf(s[j][0], s[j][1]));
            mx1 = fmaxf(mx1, fmaxf(s[j][2], s[j][3]));
        }
        mx0 = fmaxf(mx0, __shfl_xor_sync(~0u, mx0, 1));
        mx0 = fmaxf(mx0, __shfl_xor_sync(~0u, mx0, 2));
        mx1 = fmaxf(mx1, __shfl_xor_sync(~0u, mx1, 1));
        mx1 = fmaxf(mx1, __shfl_xor_sync(~0u, mx1, 2));

        const float mn0 = fmaxf(m0r, mx0), mn1 = fmaxf(m1r, mx1);
        const float al0 = __expf(m0r - mn0), al1 = __expf(m1r - mn1);
        m0r = mn0; m1r = mn1;

        float ps0 = 0.f, ps1 = 0.f;
#pragma unroll
        for (int j = 0; j < 8; j++) {
            s[j][0] = __expf(s[j][0] - mn0);
            s[j][1] = __expf(s[j][1] - mn0);
            s[j][2] = __expf(s[j][2] - mn1);
            s[j][3] = __expf(s[j][3] - mn1);
            ps0 += s[j][0] + s[j][1];
            ps1 += s[j][2] + s[j][3];
            acc_o[j][0] *= al0; acc_o[j][1] *= al0;
            acc_o[j][2] *= al1; acc_o[j][3] *= al1;
        }
        ps0 += __shfl_xor_sync(~0u, ps0, 1);
        ps0 += __shfl_xor_sync(~0u, ps0, 2);
        ps1 += __shfl_xor_sync(~0u, ps1, 1);
        ps1 += __shfl_xor_sync(~0u, ps1, 2);
        s0r = s0r * al0 + ps0;
        s1r = s1r * al1 + ps1;

        CP_WAIT0();
        __syncthreads();                 // V(ch) visible; all warps done with K(ch)
        if (ch + 1 < S_ / 64) { issueK(n0 + 64); CP_COMMIT(); }  // K(ch+1) flies during PV

        // ---- O += P @ V, single-pass fp16, P packed from registers ----
#pragma unroll
        for (int ks = 0; ks < 4; ks++) {
            uint32_t a[4];
            a[0] = pkh2(s[2 * ks][0],     s[2 * ks][1]);
            a[1] = pkh2(s[2 * ks][2],     s[2 * ks][3]);
            a[2] = pkh2(s[2 * ks + 1][0], s[2 * ks + 1][1]);
            a[3] = pkh2(s[2 * ks + 1][2], s[2 * ks + 1][3]);
            uint32_t v[4][4];
#pragma unroll
            for (int nb = 0; nb < 4; nb++)
                ldsm4(v[nb], smb + FV + SWZ((uint32_t)((rB0 + 16 * nb) * 128 + cB + ks * 32)));
#pragma unroll
            for (int j = 0; j < 8; j++) {
                uint32_t bb[2] = { v[j >> 1][(j & 1) * 2], v[j >> 1][(j & 1) * 2 + 1] };
                hmma_f16(acc_o[j], a, bb);
            }
        }
    }

    // ---- epilogue: normalize, write ctx (single fp16) ----
    const int b = bh >> 4, h = bh & 15;
    const float inv0 = 1.0f / s0r, inv1 = 1.0f / s1r;
    const int r0 = m0 + wid * 16 + g;
    const size_t ro0 = ((size_t)(b * S_ + r0)) * DM + h * DK;
    const size_t ro1 = ro0 + (size_t)8 * DM;
#pragma unroll
    for (int j = 0; j < 8; j++) {
        const int d = 8 * j + 2 * tq;
        *(uint32_t*)&g_ctx16[ro0 + d] = pkh2(acc_o[j][0] * inv0, acc_o[j][1] * inv0);
        *(uint32_t*)&g_ctx16[ro1 + d] = pkh2(acc_o[j][2] * inv1, acc_o[j][3] * inv1);
    }
}

// ---------------------------------------------------------------------------
// out: out = ctx @ Wo^T + bo.  grid (8, 32)
// ---------------------------------------------------------------------------
__global__ __launch_bounds__(256) void out_kernel(float* __restrict__ out,
                                                  const float* __restrict__ bo)
{
    extern __shared__ char sm[];
    const int n0 = blockIdx.x * 128;
    const int m0 = blockIdx.y * 128;

    float acc[2][8][4];
#pragma unroll
    for (int i = 0; i < 2; i++)
#pragma unroll
        for (int j = 0; j < 8; j++)
#pragma unroll
            for (int q = 0; q < 4; q++) acc[i][j][q] = 0.f;

    mma_loop(g_ctx16 + (size_t)m0 * DM, DM, g_Wo16 + (size_t)n0 * DM, DM, DM, sm, acc);

    const int lane = threadIdx.x & 31, wid = threadIdx.x >> 5;
    const int wm = wid >> 1, wn = wid & 1;
#pragma unroll
    for (int i = 0; i < 2; i++)
#pragma unroll
    for (int half = 0; half < 2; half++) {
        const int r = m0 + wm * 32 + i * 16 + (lane >> 2) + half * 8;
#pragma unroll
        for (int j = 0; j < 8; j++) {
            const int c = n0 + wn * 64 + j * 8 + 2 * (lane & 3);
            float2 o = { acc[i][j][half * 2] + bo[c],
                         acc[i][j][half * 2 + 1] + bo[c + 1] };
            *(float2*)(out + (size_t)r * DM + c) = o;
        }
    }
}

// ---------------------------------------------------------------------------
// launcher — no __device__ symbol referenced from host code.
// ---------------------------------------------------------------------------
extern "C" void kernel_launch(void* const* d_in, const int* in_sizes, int n_in,
                              void* d_out, int out_size)
{
    (void)in_sizes; (void)n_in; (void)out_size;
    const float* Q  = (const float*)d_in[0];
    const float* K  = (const float*)d_in[1];
    const float* V  = (const float*)d_in[2];
    const float* bq = (const float*)d_in[4];
    const float* bk = (const float*)d_in[6];
    const float* bv = (const float*)d_in[8];
    const float* bo = (const float*)d_in[10];
    float* out = (float*)d_out;

    cudaFuncSetAttribute(proj_kernel,  cudaFuncAttributeMaxDynamicSharedMemorySize, GE_SZ);
    cudaFuncSetAttribute(out_kernel,   cudaFuncAttributeMaxDynamicSharedMemorySize, GE_SZ);
    cudaFuncSetAttribute(flash_kernel, cudaFuncAttributeMaxDynamicSharedMemorySize, FL_SZ);

    const int total4 = 3 * NX4 + 4 * NW4;
    cvt_kernel<<<total4 / 256, 256>>>(Q, K, V,
                                      (const float*)d_in[3], (const float*)d_in[5],
                                      (const float*)d_in[7], (const float*)d_in[9]);

    proj_kernel <<<dim3(DM / 128, MROWS / 128, 3), 256, GE_SZ>>>(bq, bk, bv);
    flash_kernel<<<dim3(S_ / 128, BH), 256, FL_SZ>>>();
    out_kernel  <<<dim3(DM / 128, MROWS / 128),   256, GE_SZ>>>(out, bo);
}